// round 2
// baseline (speedup 1.0000x reference)
#include <cuda_runtime.h>
#include <cstdint>

#define NEXP  8
#define BATCH 4096

// ---------------- device scratch (no allocations allowed) ----------------
__device__ float g_gs1[NEXP * 32];
__device__ float g_gb1[NEXP * 32];
__device__ float g_gs2[NEXP * 64];
__device__ float g_gb2[NEXP * 64];
__device__ int   g_expid[2 * BATCH];
__device__ float g_gatev[2 * BATCH];
__device__ float g_pout[2 * BATCH * 10];

// ---------------- f32x2 packed helpers (Blackwell) ----------------
static __device__ __forceinline__ unsigned long long pack2(float x, float y) {
    unsigned long long r;
    asm("mov.b64 %0, {%1, %2};" : "=l"(r) : "r"(__float_as_uint(x)), "r"(__float_as_uint(y)));
    return r;
}
static __device__ __forceinline__ void ffma2(unsigned long long& d, unsigned long long a, unsigned long long b) {
    asm("fma.rn.f32x2 %0, %1, %2, %0;" : "+l"(d) : "l"(a), "l"(b));
}
static __device__ __forceinline__ float2 unpack2(unsigned long long v) {
    unsigned int lo, hi;
    asm("mov.b64 {%0, %1}, %2;" : "=r"(lo), "=r"(hi) : "l"(v));
    return make_float2(__uint_as_float(lo), __uint_as_float(hi));
}

// ---------------- fold BN (eval mode) into scale/shift ----------------
__global__ void eff_kernel(const float* __restrict__ b1, const float* __restrict__ g1,
                           const float* __restrict__ be1, const float* __restrict__ rm1,
                           const float* __restrict__ rv1,
                           const float* __restrict__ b2, const float* __restrict__ g2,
                           const float* __restrict__ be2, const float* __restrict__ rm2,
                           const float* __restrict__ rv2) {
    int t = threadIdx.x;
    if (t < NEXP * 32) {
        float s = g1[t] / sqrtf(rv1[t] + 1e-5f);
        g_gs1[t] = s;
        g_gb1[t] = (b1[t] - rm1[t]) * s + be1[t];
    }
    if (t < NEXP * 64) {
        float s = g2[t] / sqrtf(rv2[t] + 1e-5f);
        g_gs2[t] = s;
        g_gb2[t] = (b2[t] - rm2[t]) * s + be2[t];
    }
}

// ---------------- gating: logits, top-2, softmax, pair list ----------------
__global__ void gate_kernel(const float* __restrict__ x, const float* __restrict__ wg) {
    __shared__ float red[4][8];
    int b = blockIdx.x;
    int t = threadIdx.x;            // 128 threads
    const float* xb = x + (size_t)b * 3072;

    float p[8];
#pragma unroll
    for (int i = 0; i < 8; i++) p[i] = 0.f;

    for (int j = t; j < 3072; j += 128) {
        float xv = xb[j];
        const float4* w4 = (const float4*)(wg + (size_t)j * 8);
        float4 w0 = w4[0], w1 = w4[1];
        p[0] += xv * w0.x; p[1] += xv * w0.y; p[2] += xv * w0.z; p[3] += xv * w0.w;
        p[4] += xv * w1.x; p[5] += xv * w1.y; p[6] += xv * w1.z; p[7] += xv * w1.w;
    }
#pragma unroll
    for (int off = 16; off; off >>= 1)
#pragma unroll
        for (int i = 0; i < 8; i++) p[i] += __shfl_xor_sync(0xffffffffu, p[i], off);
    if ((t & 31) == 0)
#pragma unroll
        for (int i = 0; i < 8; i++) red[t >> 5][i] = p[i];
    __syncthreads();
    if (t == 0) {
        float lg[8];
#pragma unroll
        for (int i = 0; i < 8; i++) lg[i] = red[0][i] + red[1][i] + red[2][i] + red[3][i];
        // top-2, first-occurrence tie order (matches jax.lax.top_k)
        int i0 = 0;
#pragma unroll
        for (int e = 1; e < 8; e++) if (lg[e] > lg[i0]) i0 = e;
        int i1 = -1;
#pragma unroll
        for (int e = 0; e < 8; e++) {
            if (e == i0) continue;
            if (i1 < 0 || lg[e] > lg[i1]) i1 = e;
        }
        float t1  = expf(lg[i1] - lg[i0]);     // <= 1
        float inv = 1.f / (1.f + t1);
        g_expid[2 * b]     = i0;
        g_gatev[2 * b]     = inv;
        g_expid[2 * b + 1] = i1;
        g_gatev[2 * b + 1] = t1 * inv;
    }
}

// ---------------- fused expert kernel: one block per (sample, expert) pair ----------------
// W2T rows padded to 66 floats (even -> LDS.64 stays 8B-aligned; 66 mod 32 = 2
// -> transpose-store bank conflicts drop from 32-way to 2-way).
#define W2T_LD     66
#define W2T_FLOATS (288 * W2T_LD)                       // 19008
#define SMEM_FLOATS (W2T_FLOATS + 10368 + 3468)         // 32844 floats = ~128 KB

__global__ void __launch_bounds__(256) pair_kernel(
    const float* __restrict__ x,  const float* __restrict__ w1,
    const float* __restrict__ w2, const float* __restrict__ fcw,
    const float* __restrict__ fcb) {
    extern __shared__ float smem[];
    float* W2T = smem;                       // 19008  (transposed: [k][oc], padded rows)
    float* H1  = smem + W2T_FLOATS;          // 10368  (padded 18x18 per channel, halo = 0)
    float* XS  = smem + W2T_FLOATS + 10368;  // 3468   (padded 34x34 per channel, halo = 0)

    int p   = blockIdx.x;
    int b   = p >> 1;
    int e   = g_expid[p];
    int tid = threadIdx.x;

    // ---- phase 0: zero padded buffers ----
    for (int i = tid; i < 10368; i += 256) H1[i] = 0.f;
    for (int i = tid; i < 3468;  i += 256) XS[i] = 0.f;
    __syncthreads();

    // ---- phase 1: fill XS interior, load W2 transposed ----
    const float* xb = x + (size_t)b * 3072;
    for (int i = tid; i < 3072; i += 256) {
        int c = i >> 10, r = (i >> 5) & 31, w = i & 31;
        XS[c * 1156 + (r + 1) * 34 + (w + 1)] = xb[i];
    }
    const float* w2e = w2 + (size_t)e * 18432;
    for (int i = tid; i < 18432; i += 256) {
        int oc = i / 288, k = i - oc * 288;
        W2T[k * W2T_LD + oc] = w2e[i];
    }

    // conv1 weights (2 output channels per thread) into packed registers
    int ocp = tid >> 4;              // 0..15
    int oc0 = ocp << 1;
    unsigned long long wp1[27];
    {
        const float* wa = w1 + ((size_t)e * 32 + oc0) * 27;
#pragma unroll
        for (int j = 0; j < 27; j++) wp1[j] = pack2(wa[j], wa[27 + j]);
    }
    float s1a = g_gs1[e * 32 + oc0],     s1b = g_gs1[e * 32 + oc0 + 1];
    float q1a = g_gb1[e * 32 + oc0],     q1b = g_gb1[e * 32 + oc0 + 1];
    __syncthreads();

    // ---- phase 2: conv1 + BN + ReLU + 2x2 maxpool -> H1 (padded) ----
    {
        int ci = tid & 15;           // output column (pooled)
#pragma unroll 1
        for (int i = 0; i < 16; i++) {
            int px = ci, py = i;
            float m0 = 0.f, m1 = 0.f;   // ReLU outputs >= 0, so 0 is a valid init
#pragma unroll
            for (int d = 0; d < 4; d++) {
                int y0 = 2 * py + (d >> 1), x0 = 2 * px + (d & 1);
                const float* base = XS + y0 * 34 + x0;
                unsigned long long acc = 0ULL;   // packed (0,0)
#pragma unroll
                for (int c = 0; c < 3; c++)
#pragma unroll
                    for (int ky = 0; ky < 3; ky++)
#pragma unroll
                        for (int kx = 0; kx < 3; kx++) {
                            float a = base[c * 1156 + ky * 34 + kx];
                            ffma2(acc, pack2(a, a), wp1[c * 9 + ky * 3 + kx]);
                        }
                float2 v = unpack2(acc);
                m0 = fmaxf(m0, fmaxf(0.f, v.x * s1a + q1a));
                m1 = fmaxf(m1, fmaxf(0.f, v.y * s1b + q1b));
            }
            H1[oc0 * 324 + (py + 1) * 18 + (px + 1)]       = m0;
            H1[(oc0 + 1) * 324 + (py + 1) * 18 + (px + 1)] = m1;
        }
    }
    __syncthreads();

    // ---- phase 3: conv2 as register-tiled GEMM (M=256 spatial, N=64 oc, K=288) ----
    int tn  = tid & 7;               // oc tile: 8 channels
    int tm  = tid >> 3;              // spatial tile: 2 pooled cells = 8 conv positions
    int ocb = tn << 3;

    int offs[8];
#pragma unroll
    for (int q = 0; q < 2; q++) {
        int pc = 2 * tm + q;
        int py = pc >> 3, px = pc & 7;
#pragma unroll
        for (int d = 0; d < 4; d++)
            offs[q * 4 + d] = (2 * py + (d >> 1)) * 18 + (2 * px + (d & 1));
    }

    unsigned long long acc[8][4];
#pragma unroll
    for (int s = 0; s < 8; s++)
#pragma unroll
        for (int n = 0; n < 4; n++) acc[s][n] = 0ULL;

#pragma unroll 1
    for (int ic = 0; ic < 32; ic++) {
        const float* Hc = H1 + ic * 324;
        const float* Wkb = W2T + (ic * 9) * W2T_LD + ocb;
#pragma unroll
        for (int t9 = 0; t9 < 9; t9++) {
            const float* Ha = Hc + (t9 / 3) * 18 + (t9 % 3);
            unsigned long long ap[8];
#pragma unroll
            for (int s = 0; s < 8; s++) {
                float a = Ha[offs[s]];
                ap[s] = pack2(a, a);
            }
            const unsigned long long* brow = (const unsigned long long*)(Wkb + t9 * W2T_LD);
#pragma unroll
            for (int np = 0; np < 4; np++) {
                unsigned long long bv = brow[np];
#pragma unroll
                for (int s = 0; s < 8; s++) ffma2(acc[s][np], ap[s], bv);
            }
        }
    }

    // ---- phase 4: BN + ReLU + pool + fc partials (fc_w streamed from L2) ----
    float s2[8], q2[8];
#pragma unroll
    for (int n = 0; n < 8; n++) {
        s2[n] = g_gs2[e * 64 + ocb + n];
        q2[n] = g_gb2[e * 64 + ocb + n];
    }
    const float* fe = fcw + (size_t)e * 40960;
    float fca[10];
#pragma unroll
    for (int o = 0; o < 10; o++) fca[o] = 0.f;

#pragma unroll
    for (int q = 0; q < 2; q++) {
        int pc = 2 * tm + q;         // flat pooled position (py*8+px)
#pragma unroll
        for (int np = 0; np < 4; np++) {
            float m0 = 0.f, m1 = 0.f;
#pragma unroll
            for (int d = 0; d < 4; d++) {
                float2 v = unpack2(acc[q * 4 + d][np]);
                m0 = fmaxf(m0, fmaxf(0.f, v.x * s2[2 * np]     + q2[2 * np]));
                m1 = fmaxf(m1, fmaxf(0.f, v.y * s2[2 * np + 1] + q2[2 * np + 1]));
            }
            int j0 = (ocb + 2 * np) * 64 + pc;    // h2 flat index = oc*64 + pooled pos
#pragma unroll
            for (int o = 0; o < 10; o++)
                fca[o] += m0 * fe[o * 4096 + j0] + m1 * fe[o * 4096 + j0 + 64];
        }
    }

    // ---- phase 5: reduce fc partials across the block, write pair output ----
#pragma unroll
    for (int o = 0; o < 10; o++)
#pragma unroll
        for (int off = 16; off; off >>= 1)
            fca[o] += __shfl_xor_sync(0xffffffffu, fca[o], off);

    float* red = XS;   // reuse (XS last read in phase 2, barrier since)
    if ((tid & 31) == 0)
#pragma unroll
        for (int o = 0; o < 10; o++) red[(tid >> 5) * 10 + o] = fca[o];
    __syncthreads();
    if (tid < 10) {
        float s = 0.f;
#pragma unroll
        for (int w = 0; w < 8; w++) s += red[w * 10 + tid];
        g_pout[p * 10 + tid] = s + fcb[e * 10 + tid];
    }
}

// ---------------- combine: y = log(g0*exp(o0) + g1*exp(o1)) ----------------
__global__ void combine_kernel(float* __restrict__ out) {
    int idx = blockIdx.x * blockDim.x + threadIdx.x;
    if (idx >= BATCH * 10) return;
    int b = idx / 10, o = idx - b * 10;
    float g0 = g_gatev[2 * b], g1 = g_gatev[2 * b + 1];
    float c = g0 * expf(g_pout[(2 * b) * 10 + o]) + g1 * expf(g_pout[(2 * b + 1) * 10 + o]);
    if (c == 0.f) c = 2.2204460492503131e-16f;   // np.finfo(float).eps
    out[idx] = logf(c);
}

// ---------------- loss: CV^2(importance) + CV^2(load), deterministic ----------------
__global__ void loss_kernel(float* __restrict__ out, int out_size) {
    __shared__ float rimp[8 * 8];
    __shared__ float rcnt[8 * 8];
    int t = threadIdx.x;   // 256
    float imp[8], cnt[8];
#pragma unroll
    for (int i = 0; i < 8; i++) { imp[i] = 0.f; cnt[i] = 0.f; }
    for (int p = t; p < 2 * BATCH; p += 256) {
        int e = g_expid[p];
        imp[e] += g_gatev[p];
        cnt[e] += 1.f;
    }
#pragma unroll
    for (int off = 16; off; off >>= 1)
#pragma unroll
        for (int i = 0; i < 8; i++) {
            imp[i] += __shfl_xor_sync(0xffffffffu, imp[i], off);
            cnt[i] += __shfl_xor_sync(0xffffffffu, cnt[i], off);
        }
    if ((t & 31) == 0)
#pragma unroll
        for (int i = 0; i < 8; i++) {
            rimp[(t >> 5) * 8 + i] = imp[i];
            rcnt[(t >> 5) * 8 + i] = cnt[i];
        }
    __syncthreads();
    if (t == 0) {
        double si = 0, sl = 0, si2 = 0, sl2 = 0;
        for (int e = 0; e < 8; e++) {
            double vi = 0, vl = 0;
            for (int w = 0; w < 8; w++) { vi += rimp[w * 8 + e]; vl += rcnt[w * 8 + e]; }
            si += vi; sl += vl; si2 += vi * vi; sl2 += vl * vl;
        }
        double mi = si / 8.0, ml = sl / 8.0;
        double vari = (si2 - 8.0 * mi * mi) / 7.0;   // ddof=1
        double varl = (sl2 - 8.0 * ml * ml) / 7.0;
        double loss = (vari / (mi * mi + 1e-10) + varl / (ml * ml + 1e-10)) * 0.01;
        out[out_size - 1] = (float)loss;
    }
}

// ---------------- launch ----------------
extern "C" void kernel_launch(void* const* d_in, const int* in_sizes, int n_in,
                              void* d_out, int out_size) {
    const float* x   = (const float*)d_in[0];
    // d_in[1] = index (unused by reference math)
    const float* wg  = (const float*)d_in[2];
    const float* w1  = (const float*)d_in[3];
    const float* b1  = (const float*)d_in[4];
    const float* g1  = (const float*)d_in[5];
    const float* be1 = (const float*)d_in[6];
    const float* rm1 = (const float*)d_in[7];
    const float* rv1 = (const float*)d_in[8];
    const float* w2  = (const float*)d_in[9];
    const float* b2  = (const float*)d_in[10];
    const float* g2  = (const float*)d_in[11];
    const float* be2 = (const float*)d_in[12];
    const float* rm2 = (const float*)d_in[13];
    const float* rv2 = (const float*)d_in[14];
    const float* fcw = (const float*)d_in[15];
    const float* fcb = (const float*)d_in[16];
    float* out = (float*)d_out;

    const int smem_bytes = SMEM_FLOATS * 4;   // ~128 KB
    cudaFuncSetAttribute(pair_kernel, cudaFuncAttributeMaxDynamicSharedMemorySize, smem_bytes);

    eff_kernel<<<1, 512>>>(b1, g1, be1, rm1, rv1, b2, g2, be2, rm2, rv2);
    gate_kernel<<<BATCH, 128>>>(x, wg);
    pair_kernel<<<2 * BATCH, 256, smem_bytes>>>(x, w1, w2, fcw, fcb);
    combine_kernel<<<(BATCH * 10 + 255) / 256, 256>>>(out);
    loss_kernel<<<1, 256>>>(out, out_size);
}

// round 3
// speedup vs baseline: 1.0840x; 1.0840x over previous
#include <cuda_runtime.h>
#include <cstdint>

#define NEXP  8
#define BATCH 4096

// ---------------- device scratch (no allocations allowed) ----------------
__device__ float g_gs1[NEXP * 32];
__device__ float g_gb1[NEXP * 32];
__device__ float g_gs2[NEXP * 64];
__device__ float g_gb2[NEXP * 64];
__device__ int   g_expid[2 * BATCH];
__device__ float g_gatev[2 * BATCH];
__device__ float g_pout[2 * BATCH * 10];

// ---------------- f32x2 packed helpers (Blackwell) ----------------
static __device__ __forceinline__ unsigned long long pack2(float x, float y) {
    unsigned long long r;
    asm("mov.b64 %0, {%1, %2};" : "=l"(r) : "r"(__float_as_uint(x)), "r"(__float_as_uint(y)));
    return r;
}
static __device__ __forceinline__ void ffma2(unsigned long long& d, unsigned long long a, unsigned long long b) {
    asm("fma.rn.f32x2 %0, %1, %2, %0;" : "+l"(d) : "l"(a), "l"(b));
}
static __device__ __forceinline__ float2 unpack2(unsigned long long v) {
    unsigned int lo, hi;
    asm("mov.b64 {%0, %1}, %2;" : "=r"(lo), "=r"(hi) : "l"(v));
    return make_float2(__uint_as_float(lo), __uint_as_float(hi));
}

// ---------------- fold BN (eval mode) into scale/shift ----------------
__global__ void eff_kernel(const float* __restrict__ b1, const float* __restrict__ g1,
                           const float* __restrict__ be1, const float* __restrict__ rm1,
                           const float* __restrict__ rv1,
                           const float* __restrict__ b2, const float* __restrict__ g2,
                           const float* __restrict__ be2, const float* __restrict__ rm2,
                           const float* __restrict__ rv2) {
    int t = threadIdx.x;
    if (t < NEXP * 32) {
        float s = g1[t] / sqrtf(rv1[t] + 1e-5f);
        g_gs1[t] = s;
        g_gb1[t] = (b1[t] - rm1[t]) * s + be1[t];
    }
    if (t < NEXP * 64) {
        float s = g2[t] / sqrtf(rv2[t] + 1e-5f);
        g_gs2[t] = s;
        g_gb2[t] = (b2[t] - rm2[t]) * s + be2[t];
    }
}

// ---------------- gating: logits, top-2, softmax, pair list ----------------
__global__ void gate_kernel(const float* __restrict__ x, const float* __restrict__ wg) {
    __shared__ float red[4][8];
    int b = blockIdx.x;
    int t = threadIdx.x;            // 128 threads
    const float* xb = x + (size_t)b * 3072;

    float p[8];
#pragma unroll
    for (int i = 0; i < 8; i++) p[i] = 0.f;

    for (int j = t; j < 3072; j += 128) {
        float xv = xb[j];
        const float4* w4 = (const float4*)(wg + (size_t)j * 8);
        float4 w0 = w4[0], w1 = w4[1];
        p[0] += xv * w0.x; p[1] += xv * w0.y; p[2] += xv * w0.z; p[3] += xv * w0.w;
        p[4] += xv * w1.x; p[5] += xv * w1.y; p[6] += xv * w1.z; p[7] += xv * w1.w;
    }
#pragma unroll
    for (int off = 16; off; off >>= 1)
#pragma unroll
        for (int i = 0; i < 8; i++) p[i] += __shfl_xor_sync(0xffffffffu, p[i], off);
    if ((t & 31) == 0)
#pragma unroll
        for (int i = 0; i < 8; i++) red[t >> 5][i] = p[i];
    __syncthreads();
    if (t == 0) {
        float lg[8];
#pragma unroll
        for (int i = 0; i < 8; i++) lg[i] = red[0][i] + red[1][i] + red[2][i] + red[3][i];
        // top-2, first-occurrence tie order (matches jax.lax.top_k)
        int i0 = 0;
#pragma unroll
        for (int e = 1; e < 8; e++) if (lg[e] > lg[i0]) i0 = e;
        int i1 = -1;
#pragma unroll
        for (int e = 0; e < 8; e++) {
            if (e == i0) continue;
            if (i1 < 0 || lg[e] > lg[i1]) i1 = e;
        }
        float t1  = expf(lg[i1] - lg[i0]);     // <= 1
        float inv = 1.f / (1.f + t1);
        g_expid[2 * b]     = i0;
        g_gatev[2 * b]     = inv;
        g_expid[2 * b + 1] = i1;
        g_gatev[2 * b + 1] = t1 * inv;
    }
}

// ---------------- fused expert kernel: one block per (sample, expert) pair ----------------
// W2 is staged in 8-input-channel chunks (72 k-rows x 66-padded) so the whole
// block fits in 74.4 KB smem -> 2 blocks/SM.
#define W2C_LD     66
#define W2C_FLOATS (72 * W2C_LD)                        // 4752
#define SMEM_FLOATS (W2C_FLOATS + 10368 + 3468)         // 18588 floats = 74.4 KB

__global__ void __launch_bounds__(256, 2) pair_kernel(
    const float* __restrict__ x,  const float* __restrict__ w1,
    const float* __restrict__ w2, const float* __restrict__ fcw,
    const float* __restrict__ fcb) {
    extern __shared__ float smem[];
    float* W2C = smem;                       // 4752   (chunk: [kk][oc], padded rows)
    float* H1  = smem + W2C_FLOATS;          // 10368  (padded 18x18 per channel, halo = 0)
    float* XS  = smem + W2C_FLOATS + 10368;  // 3468   (padded 34x34 per channel, halo = 0)

    int p   = blockIdx.x;
    int b   = p >> 1;
    int e   = g_expid[p];
    int tid = threadIdx.x;

    // ---- phase 0: zero padded buffers ----
    for (int i = tid; i < 10368; i += 256) H1[i] = 0.f;
    for (int i = tid; i < 3468;  i += 256) XS[i] = 0.f;
    __syncthreads();

    // ---- phase 1: fill XS interior ----
    const float* xb = x + (size_t)b * 3072;
    for (int i = tid; i < 3072; i += 256) {
        int c = i >> 10, r = (i >> 5) & 31, w = i & 31;
        XS[c * 1156 + (r + 1) * 34 + (w + 1)] = xb[i];
    }

    // conv1 weights (2 output channels per thread) into packed registers
    int ocp = tid >> 4;              // 0..15
    int oc0 = ocp << 1;
    unsigned long long wp1[27];
    {
        const float* wa = w1 + ((size_t)e * 32 + oc0) * 27;
#pragma unroll
        for (int j = 0; j < 27; j++) wp1[j] = pack2(wa[j], wa[27 + j]);
    }
    float s1a = g_gs1[e * 32 + oc0],     s1b = g_gs1[e * 32 + oc0 + 1];
    float q1a = g_gb1[e * 32 + oc0],     q1b = g_gb1[e * 32 + oc0 + 1];
    __syncthreads();

    // ---- phase 2: conv1 + BN + ReLU + 2x2 maxpool -> H1 (padded) ----
    // Per pooled output, load the 4x4 input patch per channel into registers
    // once (48 LDS) and feed all 4 pool positions' FFMA2 from registers.
    {
        int ci = tid & 15;           // output column (pooled)
#pragma unroll 1
        for (int i = 0; i < 16; i++) {
            int px = ci, py = i;
            unsigned long long acc[4];
#pragma unroll
            for (int d = 0; d < 4; d++) acc[d] = 0ULL;
#pragma unroll
            for (int c = 0; c < 3; c++) {
                const float* Pc = XS + c * 1156 + (2 * py) * 34 + (2 * px);
                float patch[16];
#pragma unroll
                for (int ty = 0; ty < 4; ty++)
#pragma unroll
                    for (int tx = 0; tx < 4; tx++)
                        patch[ty * 4 + tx] = Pc[ty * 34 + tx];
#pragma unroll
                for (int d = 0; d < 4; d++) {
                    int dy = d >> 1, dx = d & 1;
#pragma unroll
                    for (int ky = 0; ky < 3; ky++)
#pragma unroll
                        for (int kx = 0; kx < 3; kx++) {
                            float a = patch[(dy + ky) * 4 + (dx + kx)];
                            ffma2(acc[d], pack2(a, a), wp1[c * 9 + ky * 3 + kx]);
                        }
                }
            }
            float m0 = 0.f, m1 = 0.f;   // ReLU outputs >= 0, so 0 is a valid init
#pragma unroll
            for (int d = 0; d < 4; d++) {
                float2 v = unpack2(acc[d]);
                m0 = fmaxf(m0, fmaxf(0.f, v.x * s1a + q1a));
                m1 = fmaxf(m1, fmaxf(0.f, v.y * s1b + q1b));
            }
            H1[oc0 * 324 + (py + 1) * 18 + (px + 1)]       = m0;
            H1[(oc0 + 1) * 324 + (py + 1) * 18 + (px + 1)] = m1;
        }
    }
    __syncthreads();

    // ---- phase 3: conv2 as register-tiled GEMM (M=256 spatial, N=64 oc, K=288) ----
    // K processed in 4 chunks of 8 input channels; W2 chunk staged transposed.
    int tn  = tid & 7;               // oc tile: 8 channels
    int tm  = tid >> 3;              // spatial tile: 2 pooled cells = 8 conv positions
    int ocb = tn << 3;

    int offs[8];
#pragma unroll
    for (int q = 0; q < 2; q++) {
        int pc = 2 * tm + q;
        int py = pc >> 3, px = pc & 7;
#pragma unroll
        for (int d = 0; d < 4; d++)
            offs[q * 4 + d] = (2 * py + (d >> 1)) * 18 + (2 * px + (d & 1));
    }

    unsigned long long acc[8][4];
#pragma unroll
    for (int s = 0; s < 8; s++)
#pragma unroll
        for (int n = 0; n < 4; n++) acc[s][n] = 0ULL;

    const float* w2e = w2 + (size_t)e * 18432;

#pragma unroll 1
    for (int ch = 0; ch < 4; ch++) {
        // stage chunk: k-rows [72*ch, 72*ch+72), transposed [kk][oc] with padded rows
#pragma unroll
        for (int j = 0; j < 18; j++) {
            int i  = tid + j * 256;          // 0..4607 over (oc, kk)
            int oc = i / 72, kk = i - oc * 72;
            W2C[kk * W2C_LD + oc] = w2e[oc * 288 + ch * 72 + kk];
        }
        __syncthreads();

#pragma unroll 1
        for (int icl = 0; icl < 8; icl++) {
            const float* Hc  = H1 + (ch * 8 + icl) * 324;
            const float* Wkb = W2C + (icl * 9) * W2C_LD + ocb;
#pragma unroll
            for (int t9 = 0; t9 < 9; t9++) {
                const float* Ha = Hc + (t9 / 3) * 18 + (t9 % 3);
                unsigned long long ap[8];
#pragma unroll
                for (int s = 0; s < 8; s++) {
                    float a = Ha[offs[s]];
                    ap[s] = pack2(a, a);
                }
                const unsigned long long* brow = (const unsigned long long*)(Wkb + t9 * W2C_LD);
#pragma unroll
                for (int np = 0; np < 4; np++) {
                    unsigned long long bv = brow[np];
#pragma unroll
                    for (int s = 0; s < 8; s++) ffma2(acc[s][np], ap[s], bv);
                }
            }
        }
        __syncthreads();
    }

    // ---- phase 4: BN + ReLU + pool + fc partials (fc_w streamed from L2) ----
    float s2[8], q2[8];
#pragma unroll
    for (int n = 0; n < 8; n++) {
        s2[n] = g_gs2[e * 64 + ocb + n];
        q2[n] = g_gb2[e * 64 + ocb + n];
    }
    const float* fe = fcw + (size_t)e * 40960;
    float fca[10];
#pragma unroll
    for (int o = 0; o < 10; o++) fca[o] = 0.f;

#pragma unroll
    for (int q = 0; q < 2; q++) {
        int pc = 2 * tm + q;         // flat pooled position (py*8+px)
#pragma unroll
        for (int np = 0; np < 4; np++) {
            float m0 = 0.f, m1 = 0.f;
#pragma unroll
            for (int d = 0; d < 4; d++) {
                float2 v = unpack2(acc[q * 4 + d][np]);
                m0 = fmaxf(m0, fmaxf(0.f, v.x * s2[2 * np]     + q2[2 * np]));
                m1 = fmaxf(m1, fmaxf(0.f, v.y * s2[2 * np + 1] + q2[2 * np + 1]));
            }
            int j0 = (ocb + 2 * np) * 64 + pc;    // h2 flat index = oc*64 + pooled pos
#pragma unroll
            for (int o = 0; o < 10; o++)
                fca[o] += m0 * fe[o * 4096 + j0] + m1 * fe[o * 4096 + j0 + 64];
        }
    }

    // ---- phase 5: reduce fc partials across the block, write pair output ----
#pragma unroll
    for (int o = 0; o < 10; o++)
#pragma unroll
        for (int off = 16; off; off >>= 1)
            fca[o] += __shfl_xor_sync(0xffffffffu, fca[o], off);

    float* red = XS;   // reuse (XS last read in phase 2, barrier since)
    if ((tid & 31) == 0)
#pragma unroll
        for (int o = 0; o < 10; o++) red[(tid >> 5) * 10 + o] = fca[o];
    __syncthreads();
    if (tid < 10) {
        float s = 0.f;
#pragma unroll
        for (int w = 0; w < 8; w++) s += red[w * 10 + tid];
        g_pout[p * 10 + tid] = s + fcb[e * 10 + tid];
    }
}

// ---------------- combine: y = log(g0*exp(o0) + g1*exp(o1)) ----------------
__global__ void combine_kernel(float* __restrict__ out) {
    int idx = blockIdx.x * blockDim.x + threadIdx.x;
    if (idx >= BATCH * 10) return;
    int b = idx / 10, o = idx - b * 10;
    float g0 = g_gatev[2 * b], g1 = g_gatev[2 * b + 1];
    float c = g0 * expf(g_pout[(2 * b) * 10 + o]) + g1 * expf(g_pout[(2 * b + 1) * 10 + o]);
    if (c == 0.f) c = 2.2204460492503131e-16f;   // np.finfo(float).eps
    out[idx] = logf(c);
}

// ---------------- loss: CV^2(importance) + CV^2(load), deterministic ----------------
__global__ void loss_kernel(float* __restrict__ out, int out_size) {
    __shared__ float rimp[8 * 8];
    __shared__ float rcnt[8 * 8];
    int t = threadIdx.x;   // 256
    float imp[8], cnt[8];
#pragma unroll
    for (int i = 0; i < 8; i++) { imp[i] = 0.f; cnt[i] = 0.f; }
    for (int p = t; p < 2 * BATCH; p += 256) {
        int e = g_expid[p];
        imp[e] += g_gatev[p];
        cnt[e] += 1.f;
    }
#pragma unroll
    for (int off = 16; off; off >>= 1)
#pragma unroll
        for (int i = 0; i < 8; i++) {
            imp[i] += __shfl_xor_sync(0xffffffffu, imp[i], off);
            cnt[i] += __shfl_xor_sync(0xffffffffu, cnt[i], off);
        }
    if ((t & 31) == 0)
#pragma unroll
        for (int i = 0; i < 8; i++) {
            rimp[(t >> 5) * 8 + i] = imp[i];
            rcnt[(t >> 5) * 8 + i] = cnt[i];
        }
    __syncthreads();
    if (t == 0) {
        double si = 0, sl = 0, si2 = 0, sl2 = 0;
        for (int e = 0; e < 8; e++) {
            double vi = 0, vl = 0;
            for (int w = 0; w < 8; w++) { vi += rimp[w * 8 + e]; vl += rcnt[w * 8 + e]; }
            si += vi; sl += vl; si2 += vi * vi; sl2 += vl * vl;
        }
        double mi = si / 8.0, ml = sl / 8.0;
        double vari = (si2 - 8.0 * mi * mi) / 7.0;   // ddof=1
        double varl = (sl2 - 8.0 * ml * ml) / 7.0;
        double loss = (vari / (mi * mi + 1e-10) + varl / (ml * ml + 1e-10)) * 0.01;
        out[out_size - 1] = (float)loss;
    }
}

// ---------------- launch ----------------
extern "C" void kernel_launch(void* const* d_in, const int* in_sizes, int n_in,
                              void* d_out, int out_size) {
    const float* x   = (const float*)d_in[0];
    // d_in[1] = index (unused by reference math)
    const float* wg  = (const float*)d_in[2];
    const float* w1  = (const float*)d_in[3];
    const float* b1  = (const float*)d_in[4];
    const float* g1  = (const float*)d_in[5];
    const float* be1 = (const float*)d_in[6];
    const float* rm1 = (const float*)d_in[7];
    const float* rv1 = (const float*)d_in[8];
    const float* w2  = (const float*)d_in[9];
    const float* b2  = (const float*)d_in[10];
    const float* g2  = (const float*)d_in[11];
    const float* be2 = (const float*)d_in[12];
    const float* rm2 = (const float*)d_in[13];
    const float* rv2 = (const float*)d_in[14];
    const float* fcw = (const float*)d_in[15];
    const float* fcb = (const float*)d_in[16];
    float* out = (float*)d_out;

    const int smem_bytes = SMEM_FLOATS * 4;   // ~74.4 KB
    cudaFuncSetAttribute(pair_kernel, cudaFuncAttributeMaxDynamicSharedMemorySize, smem_bytes);

    eff_kernel<<<1, 512>>>(b1, g1, be1, rm1, rv1, b2, g2, be2, rm2, rv2);
    gate_kernel<<<BATCH, 128>>>(x, wg);
    pair_kernel<<<2 * BATCH, 256, smem_bytes>>>(x, w1, w2, fcw, fcb);
    combine_kernel<<<(BATCH * 10 + 255) / 256, 256>>>(out);
    loss_kernel<<<1, 256>>>(out, out_size);
}

// round 4
// speedup vs baseline: 1.1186x; 1.0319x over previous
#include <cuda_runtime.h>
#include <cstdint>

#define NEXP  8
#define BATCH 4096

// ---------------- device scratch (no allocations allowed) ----------------
__device__ float g_gs1[NEXP * 32];
__device__ float g_gb1[NEXP * 32];
__device__ float g_gs2[NEXP * 64];
__device__ float g_gb2[NEXP * 64];
__device__ int   g_expid[2 * BATCH];
__device__ float g_gatev[2 * BATCH];
__device__ float g_pout[2 * BATCH * 10];

// ---------------- f32x2 packed helpers (Blackwell) ----------------
static __device__ __forceinline__ unsigned long long pack2(float x, float y) {
    unsigned long long r;
    asm("mov.b64 %0, {%1, %2};" : "=l"(r) : "r"(__float_as_uint(x)), "r"(__float_as_uint(y)));
    return r;
}
static __device__ __forceinline__ void ffma2(unsigned long long& d, unsigned long long a, unsigned long long b) {
    asm("fma.rn.f32x2 %0, %1, %2, %0;" : "+l"(d) : "l"(a), "l"(b));
}
static __device__ __forceinline__ float2 unpack2(unsigned long long v) {
    unsigned int lo, hi;
    asm("mov.b64 {%0, %1}, %2;" : "=r"(lo), "=r"(hi) : "l"(v));
    return make_float2(__uint_as_float(lo), __uint_as_float(hi));
}

// ---------------- fold BN (eval mode) into scale/shift ----------------
__global__ void eff_kernel(const float* __restrict__ b1, const float* __restrict__ g1,
                           const float* __restrict__ be1, const float* __restrict__ rm1,
                           const float* __restrict__ rv1,
                           const float* __restrict__ b2, const float* __restrict__ g2,
                           const float* __restrict__ be2, const float* __restrict__ rm2,
                           const float* __restrict__ rv2) {
    int t = threadIdx.x;
    if (t < NEXP * 32) {
        float s = g1[t] / sqrtf(rv1[t] + 1e-5f);
        g_gs1[t] = s;
        g_gb1[t] = (b1[t] - rm1[t]) * s + be1[t];
    }
    if (t < NEXP * 64) {
        float s = g2[t] / sqrtf(rv2[t] + 1e-5f);
        g_gs2[t] = s;
        g_gb2[t] = (b2[t] - rm2[t]) * s + be2[t];
    }
}

// ---------------- gating: logits, top-2, softmax, pair list ----------------
__global__ void gate_kernel(const float* __restrict__ x, const float* __restrict__ wg) {
    __shared__ float red[4][8];
    int b = blockIdx.x;
    int t = threadIdx.x;            // 128 threads
    const float* xb = x + (size_t)b * 3072;

    float p[8];
#pragma unroll
    for (int i = 0; i < 8; i++) p[i] = 0.f;

    for (int j = t; j < 3072; j += 128) {
        float xv = xb[j];
        const float4* w4 = (const float4*)(wg + (size_t)j * 8);
        float4 w0 = w4[0], w1 = w4[1];
        p[0] += xv * w0.x; p[1] += xv * w0.y; p[2] += xv * w0.z; p[3] += xv * w0.w;
        p[4] += xv * w1.x; p[5] += xv * w1.y; p[6] += xv * w1.z; p[7] += xv * w1.w;
    }
#pragma unroll
    for (int off = 16; off; off >>= 1)
#pragma unroll
        for (int i = 0; i < 8; i++) p[i] += __shfl_xor_sync(0xffffffffu, p[i], off);
    if ((t & 31) == 0)
#pragma unroll
        for (int i = 0; i < 8; i++) red[t >> 5][i] = p[i];
    __syncthreads();
    if (t == 0) {
        float lg[8];
#pragma unroll
        for (int i = 0; i < 8; i++) lg[i] = red[0][i] + red[1][i] + red[2][i] + red[3][i];
        // top-2, first-occurrence tie order (matches jax.lax.top_k)
        int i0 = 0;
#pragma unroll
        for (int e = 1; e < 8; e++) if (lg[e] > lg[i0]) i0 = e;
        int i1 = -1;
#pragma unroll
        for (int e = 0; e < 8; e++) {
            if (e == i0) continue;
            if (i1 < 0 || lg[e] > lg[i1]) i1 = e;
        }
        float t1  = expf(lg[i1] - lg[i0]);     // <= 1
        float inv = 1.f / (1.f + t1);
        g_expid[2 * b]     = i0;
        g_gatev[2 * b]     = inv;
        g_expid[2 * b + 1] = i1;
        g_gatev[2 * b + 1] = t1 * inv;
    }
}

// ---------------- fused expert kernel: one block per (sample, expert) pair ----------------
// W2 is staged in 8-input-channel chunks (72 k-rows x 66-padded) so the whole
// block fits in 74.4 KB smem -> 2 blocks/SM.
#define W2C_LD     66
#define W2C_FLOATS (72 * W2C_LD)                        // 4752
#define SMEM_FLOATS (W2C_FLOATS + 10368 + 3468)         // 18588 floats = 74.4 KB

__global__ void __launch_bounds__(256, 2) pair_kernel(
    const float* __restrict__ x,  const float* __restrict__ w1,
    const float* __restrict__ w2, const float* __restrict__ fcw,
    const float* __restrict__ fcb) {
    extern __shared__ float smem[];
    float* W2C = smem;                       // 4752   (chunk: [kk][oc], padded rows)
    float* H1  = smem + W2C_FLOATS;          // 10368  (padded 18x18 per channel, halo = 0)
    float* XS  = smem + W2C_FLOATS + 10368;  // 3468   (padded 34x34 per channel, halo = 0)

    int p   = blockIdx.x;
    int b   = p >> 1;
    int e   = g_expid[p];
    int tid = threadIdx.x;

    // ---- phase 0: zero padded buffers ----
    for (int i = tid; i < 10368; i += 256) H1[i] = 0.f;
    for (int i = tid; i < 3468;  i += 256) XS[i] = 0.f;
    __syncthreads();

    // ---- phase 1: fill XS interior ----
    const float* xb = x + (size_t)b * 3072;
    for (int i = tid; i < 3072; i += 256) {
        int c = i >> 10, r = (i >> 5) & 31, w = i & 31;
        XS[c * 1156 + (r + 1) * 34 + (w + 1)] = xb[i];
    }

    // conv1 weights (2 output channels per thread) into packed registers
    int ocp = tid >> 4;              // 0..15
    int oc0 = ocp << 1;
    unsigned long long wp1[27];
    {
        const float* wa = w1 + ((size_t)e * 32 + oc0) * 27;
#pragma unroll
        for (int j = 0; j < 27; j++) wp1[j] = pack2(wa[j], wa[27 + j]);
    }
    float s1a = g_gs1[e * 32 + oc0],     s1b = g_gs1[e * 32 + oc0 + 1];
    float q1a = g_gb1[e * 32 + oc0],     q1b = g_gb1[e * 32 + oc0 + 1];
    __syncthreads();

    // ---- phase 2: conv1 + BN + ReLU + 2x2 maxpool -> H1 (padded) ----
    // Per pooled output, load the 4x4 input patch per channel into registers
    // once (48 LDS) and feed all 4 pool positions' FFMA2 from registers.
    {
        int ci = tid & 15;           // output column (pooled)
#pragma unroll 1
        for (int i = 0; i < 16; i++) {
            int px = ci, py = i;
            unsigned long long acc1[4];
#pragma unroll
            for (int d = 0; d < 4; d++) acc1[d] = 0ULL;
#pragma unroll
            for (int c = 0; c < 3; c++) {
                const float* Pc = XS + c * 1156 + (2 * py) * 34 + (2 * px);
                float patch[16];
#pragma unroll
                for (int ty = 0; ty < 4; ty++)
#pragma unroll
                    for (int tx = 0; tx < 4; tx++)
                        patch[ty * 4 + tx] = Pc[ty * 34 + tx];
#pragma unroll
                for (int d = 0; d < 4; d++) {
                    int dy = d >> 1, dx = d & 1;
#pragma unroll
                    for (int ky = 0; ky < 3; ky++)
#pragma unroll
                        for (int kx = 0; kx < 3; kx++) {
                            float a = patch[(dy + ky) * 4 + (dx + kx)];
                            ffma2(acc1[d], pack2(a, a), wp1[c * 9 + ky * 3 + kx]);
                        }
                }
            }
            float m0 = 0.f, m1 = 0.f;   // ReLU outputs >= 0, so 0 is a valid init
#pragma unroll
            for (int d = 0; d < 4; d++) {
                float2 v = unpack2(acc1[d]);
                m0 = fmaxf(m0, fmaxf(0.f, v.x * s1a + q1a));
                m1 = fmaxf(m1, fmaxf(0.f, v.y * s1b + q1b));
            }
            H1[oc0 * 324 + (py + 1) * 18 + (px + 1)]       = m0;
            H1[(oc0 + 1) * 324 + (py + 1) * 18 + (px + 1)] = m1;
        }
    }
    __syncthreads();

    // ---- phase 3: conv2 as register-tiled GEMM (M=256 spatial, N=64 oc, K=288) ----
    // K processed in 4 chunks of 8 input channels; W2 chunk staged transposed.
    // Per input channel: each thread loads its two 4x4 H1 patches into
    // registers via aligned LDS.64 (rows are even*18 + even -> 8B aligned),
    // then all 9 taps run from registers. B rows hoisted per tap.
    int tn  = tid & 7;               // oc tile: 8 channels
    int tm  = tid >> 3;              // spatial tile: 2 pooled cells = 8 conv positions
    int ocb = tn << 3;

    unsigned long long acc[8][4];
#pragma unroll
    for (int s = 0; s < 8; s++)
#pragma unroll
        for (int n = 0; n < 4; n++) acc[s][n] = 0ULL;

    const float* w2e = w2 + (size_t)e * 18432;

    int pbase[2];
#pragma unroll
    for (int q = 0; q < 2; q++) {
        int pc = 2 * tm + q;
        int py = pc >> 3, px = pc & 7;
        pbase[q] = (2 * py) * 18 + 2 * px;
    }

#pragma unroll 1
    for (int ch = 0; ch < 4; ch++) {
        // stage chunk: k-rows [72*ch, 72*ch+72), transposed [kk][oc] with padded rows
#pragma unroll
        for (int j = 0; j < 18; j++) {
            int i  = tid + j * 256;          // 0..4607 over (oc, kk)
            int oc = i / 72, kk = i - oc * 72;
            W2C[kk * W2C_LD + oc] = w2e[oc * 288 + ch * 72 + kk];
        }
        __syncthreads();

#pragma unroll 1
        for (int icl = 0; icl < 8; icl++) {
            const float* Hc  = H1 + (ch * 8 + icl) * 324;
            const float* Wkb = W2C + (icl * 9) * W2C_LD + ocb;

            // load both 4x4 patches (aligned float2 pairs)
            float pt[2][16];
#pragma unroll
            for (int q = 0; q < 2; q++) {
                const float* base = Hc + pbase[q];
#pragma unroll
                for (int r = 0; r < 4; r++) {
                    float2 u = *(const float2*)(base + r * 18);
                    float2 v = *(const float2*)(base + r * 18 + 2);
                    pt[q][r * 4 + 0] = u.x; pt[q][r * 4 + 1] = u.y;
                    pt[q][r * 4 + 2] = v.x; pt[q][r * 4 + 3] = v.y;
                }
            }

#pragma unroll
            for (int t9 = 0; t9 < 9; t9++) {
                int ky = t9 / 3, kx = t9 % 3;
                const unsigned long long* brow = (const unsigned long long*)(Wkb + t9 * W2C_LD);
                unsigned long long bv0 = brow[0], bv1 = brow[1], bv2 = brow[2], bv3 = brow[3];
#pragma unroll
                for (int q = 0; q < 2; q++)
#pragma unroll
                    for (int d = 0; d < 4; d++) {
                        float a = pt[q][((d >> 1) + ky) * 4 + (d & 1) + kx];
                        unsigned long long ap = pack2(a, a);
                        int s = q * 4 + d;
                        ffma2(acc[s][0], ap, bv0);
                        ffma2(acc[s][1], ap, bv1);
                        ffma2(acc[s][2], ap, bv2);
                        ffma2(acc[s][3], ap, bv3);
                    }
            }
        }
        __syncthreads();
    }

    // ---- phase 4: BN + ReLU + pool + fc partials (fc_w streamed from L2) ----
    float s2[8], q2[8];
#pragma unroll
    for (int n = 0; n < 8; n++) {
        s2[n] = g_gs2[e * 64 + ocb + n];
        q2[n] = g_gb2[e * 64 + ocb + n];
    }
    const float* fe = fcw + (size_t)e * 40960;
    float fca[10];
#pragma unroll
    for (int o = 0; o < 10; o++) fca[o] = 0.f;

#pragma unroll
    for (int q = 0; q < 2; q++) {
        int pc = 2 * tm + q;         // flat pooled position (py*8+px)
#pragma unroll
        for (int np = 0; np < 4; np++) {
            float m0 = 0.f, m1 = 0.f;
#pragma unroll
            for (int d = 0; d < 4; d++) {
                float2 v = unpack2(acc[q * 4 + d][np]);
                m0 = fmaxf(m0, fmaxf(0.f, v.x * s2[2 * np]     + q2[2 * np]));
                m1 = fmaxf(m1, fmaxf(0.f, v.y * s2[2 * np + 1] + q2[2 * np + 1]));
            }
            int j0 = (ocb + 2 * np) * 64 + pc;    // h2 flat index = oc*64 + pooled pos
#pragma unroll
            for (int o = 0; o < 10; o++)
                fca[o] += m0 * fe[o * 4096 + j0] + m1 * fe[o * 4096 + j0 + 64];
        }
    }

    // ---- phase 5: reduce fc partials across the block, write pair output ----
#pragma unroll
    for (int o = 0; o < 10; o++)
#pragma unroll
        for (int off = 16; off; off >>= 1)
            fca[o] += __shfl_xor_sync(0xffffffffu, fca[o], off);

    float* red = XS;   // reuse (XS last read in phase 2, barrier since)
    if ((tid & 31) == 0)
#pragma unroll
        for (int o = 0; o < 10; o++) red[(tid >> 5) * 10 + o] = fca[o];
    __syncthreads();
    if (tid < 10) {
        float s = 0.f;
#pragma unroll
        for (int w = 0; w < 8; w++) s += red[w * 10 + tid];
        g_pout[p * 10 + tid] = s + fcb[e * 10 + tid];
    }
}

// ---------------- combine: y = log(g0*exp(o0) + g1*exp(o1)) ----------------
__global__ void combine_kernel(float* __restrict__ out) {
    int idx = blockIdx.x * blockDim.x + threadIdx.x;
    if (idx >= BATCH * 10) return;
    int b = idx / 10, o = idx - b * 10;
    float g0 = g_gatev[2 * b], g1 = g_gatev[2 * b + 1];
    float c = g0 * expf(g_pout[(2 * b) * 10 + o]) + g1 * expf(g_pout[(2 * b + 1) * 10 + o]);
    if (c == 0.f) c = 2.2204460492503131e-16f;   // np.finfo(float).eps
    out[idx] = logf(c);
}

// ---------------- loss: CV^2(importance) + CV^2(load), deterministic ----------------
__global__ void loss_kernel(float* __restrict__ out, int out_size) {
    __shared__ float rimp[8 * 8];
    __shared__ float rcnt[8 * 8];
    int t = threadIdx.x;   // 256
    float imp[8], cnt[8];
#pragma unroll
    for (int i = 0; i < 8; i++) { imp[i] = 0.f; cnt[i] = 0.f; }
    for (int p = t; p < 2 * BATCH; p += 256) {
        int e = g_expid[p];
        imp[e] += g_gatev[p];
        cnt[e] += 1.f;
    }
#pragma unroll
    for (int off = 16; off; off >>= 1)
#pragma unroll
        for (int i = 0; i < 8; i++) {
            imp[i] += __shfl_xor_sync(0xffffffffu, imp[i], off);
            cnt[i] += __shfl_xor_sync(0xffffffffu, cnt[i], off);
        }
    if ((t & 31) == 0)
#pragma unroll
        for (int i = 0; i < 8; i++) {
            rimp[(t >> 5) * 8 + i] = imp[i];
            rcnt[(t >> 5) * 8 + i] = cnt[i];
        }
    __syncthreads();
    if (t == 0) {
        double si = 0, sl = 0, si2 = 0, sl2 = 0;
        for (int e = 0; e < 8; e++) {
            double vi = 0, vl = 0;
            for (int w = 0; w < 8; w++) { vi += rimp[w * 8 + e]; vl += rcnt[w * 8 + e]; }
            si += vi; sl += vl; si2 += vi * vi; sl2 += vl * vl;
        }
        double mi = si / 8.0, ml = sl / 8.0;
        double vari = (si2 - 8.0 * mi * mi) / 7.0;   // ddof=1
        double varl = (sl2 - 8.0 * ml * ml) / 7.0;
        double loss = (vari / (mi * mi + 1e-10) + varl / (ml * ml + 1e-10)) * 0.01;
        out[out_size - 1] = (float)loss;
    }
}

// ---------------- launch ----------------
extern "C" void kernel_launch(void* const* d_in, const int* in_sizes, int n_in,
                              void* d_out, int out_size) {
    const float* x   = (const float*)d_in[0];
    // d_in[1] = index (unused by reference math)
    const float* wg  = (const float*)d_in[2];
    const float* w1  = (const float*)d_in[3];
    const float* b1  = (const float*)d_in[4];
    const float* g1  = (const float*)d_in[5];
    const float* be1 = (const float*)d_in[6];
    const float* rm1 = (const float*)d_in[7];
    const float* rv1 = (const float*)d_in[8];
    const float* w2  = (const float*)d_in[9];
    const float* b2  = (const float*)d_in[10];
    const float* g2  = (const float*)d_in[11];
    const float* be2 = (const float*)d_in[12];
    const float* rm2 = (const float*)d_in[13];
    const float* rv2 = (const float*)d_in[14];
    const float* fcw = (const float*)d_in[15];
    const float* fcb = (const float*)d_in[16];
    float* out = (float*)d_out;

    const int smem_bytes = SMEM_FLOATS * 4;   // ~74.4 KB
    cudaFuncSetAttribute(pair_kernel, cudaFuncAttributeMaxDynamicSharedMemorySize, smem_bytes);

    eff_kernel<<<1, 512>>>(b1, g1, be1, rm1, rv1, b2, g2, be2, rm2, rv2);
    gate_kernel<<<BATCH, 128>>>(x, wg);
    pair_kernel<<<2 * BATCH, 256, smem_bytes>>>(x, w1, w2, fcw, fcb);
    combine_kernel<<<(BATCH * 10 + 255) / 256, 256>>>(out);
    loss_kernel<<<1, 256>>>(out, out_size);
}

// round 6
// speedup vs baseline: 2.0130x; 1.7996x over previous
#include <cuda_runtime.h>
#include <cuda_bf16.h>
#include <cstdint>

#define NEXP  8
#define BATCH 4096

// ---------------- device scratch (no allocations allowed) ----------------
__device__ float g_gs1[NEXP * 32];
__device__ float g_gb1[NEXP * 32];
__device__ float g_gs2[NEXP * 64];
__device__ float g_gb2[NEXP * 64];
__device__ int   g_expid[2 * BATCH];
__device__ float g_gatev[2 * BATCH];
__device__ float g_pout[2 * BATCH * 10];
// W2 pre-split to bf16 hi/lo, tap-major: [e][tap][oc][hi(ic0..31) lo(ic0..31)]
__device__ __nv_bfloat16 g_w2bf[NEXP * 9 * 64 * 64];

// ---------------- f32x2 packed helpers (Blackwell) ----------------
static __device__ __forceinline__ unsigned long long pack2(float x, float y) {
    unsigned long long r;
    asm("mov.b64 %0, {%1, %2};" : "=l"(r) : "r"(__float_as_uint(x)), "r"(__float_as_uint(y)));
    return r;
}
static __device__ __forceinline__ void ffma2(unsigned long long& d, unsigned long long a, unsigned long long b) {
    asm("fma.rn.f32x2 %0, %1, %2, %0;" : "+l"(d) : "l"(a), "l"(b));
}
static __device__ __forceinline__ float2 unpack2(unsigned long long v) {
    unsigned int lo, hi;
    asm("mov.b64 {%0, %1}, %2;" : "=r"(lo), "=r"(hi) : "l"(v));
    return make_float2(__uint_as_float(lo), __uint_as_float(hi));
}

// ---------------- smem / mma helpers ----------------
static __device__ __forceinline__ uint32_t smem_u32(const void* p) {
    uint32_t a;
    asm("{ .reg .u64 t; cvta.to.shared.u64 t, %1; cvt.u32.u64 %0, t; }" : "=r"(a) : "l"(p));
    return a;
}
static __device__ __forceinline__ void sts32(uint32_t a, uint32_t v) {
    asm volatile("st.shared.b32 [%0], %1;" :: "r"(a), "r"(v) : "memory");
}
static __device__ __forceinline__ void sts128(uint32_t a, uint4 v) {
    asm volatile("st.shared.v4.b32 [%0], {%1,%2,%3,%4};" :: "r"(a), "r"(v.x), "r"(v.y), "r"(v.z), "r"(v.w) : "memory");
}
static __device__ __forceinline__ void ldm4(uint32_t* r, uint32_t addr) {
    asm volatile("ldmatrix.sync.aligned.m8n8.x4.shared.b16 {%0,%1,%2,%3}, [%4];"
                 : "=r"(r[0]), "=r"(r[1]), "=r"(r[2]), "=r"(r[3]) : "r"(addr));
}
static __device__ __forceinline__ void mma16816(float* d, const uint32_t* a, const uint32_t* b) {
    asm volatile("mma.sync.aligned.m16n8k16.row.col.f32.bf16.bf16.f32 "
                 "{%0,%1,%2,%3}, {%4,%5,%6,%7}, {%8,%9}, {%0,%1,%2,%3};"
                 : "+f"(d[0]), "+f"(d[1]), "+f"(d[2]), "+f"(d[3])
                 : "r"(a[0]), "r"(a[1]), "r"(a[2]), "r"(a[3]), "r"(b[0]), "r"(b[1]));
}

// ---------------- fold BN (eval mode) into scale/shift ----------------
__global__ void eff_kernel(const float* __restrict__ b1, const float* __restrict__ g1,
                           const float* __restrict__ be1, const float* __restrict__ rm1,
                           const float* __restrict__ rv1,
                           const float* __restrict__ b2, const float* __restrict__ g2,
                           const float* __restrict__ be2, const float* __restrict__ rm2,
                           const float* __restrict__ rv2) {
    int t = threadIdx.x;
    if (t < NEXP * 32) {
        float s = g1[t] / sqrtf(rv1[t] + 1e-5f);
        g_gs1[t] = s;
        g_gb1[t] = (b1[t] - rm1[t]) * s + be1[t];
    }
    if (t < NEXP * 64) {
        float s = g2[t] / sqrtf(rv2[t] + 1e-5f);
        g_gs2[t] = s;
        g_gb2[t] = (b2[t] - rm2[t]) * s + be2[t];
    }
}

// ---------------- prep: split W2 into bf16 hi/lo, tap-major ----------------
__global__ void w2bf_kernel(const float* __restrict__ w2) {
    int idx = blockIdx.x * 256 + threadIdx.x;      // 147456 total
    if (idx >= NEXP * 9 * 64 * 32) return;
    int ic  = idx & 31;
    int oc  = (idx >> 5) & 63;
    int r   = idx >> 11;
    int tap = r % 9;
    int e   = r / 9;
    float w = w2[(((size_t)e * 64 + oc) * 32 + ic) * 9 + tap];
    __nv_bfloat16 hi = __float2bfloat16(w);
    __nv_bfloat16 lo = __float2bfloat16(w - __bfloat162float(hi));
    size_t base = ((size_t)(e * 9 + tap) * 64 + oc) * 64;
    g_w2bf[base + ic]      = hi;
    g_w2bf[base + 32 + ic] = lo;
}

// ---------------- gating: logits, top-2, softmax, pair list ----------------
__global__ void gate_kernel(const float* __restrict__ x, const float* __restrict__ wg) {
    __shared__ float red[4][8];
    int b = blockIdx.x;
    int t = threadIdx.x;            // 128 threads
    const float* xb = x + (size_t)b * 3072;

    float p[8];
#pragma unroll
    for (int i = 0; i < 8; i++) p[i] = 0.f;

    for (int j = t; j < 3072; j += 128) {
        float xv = xb[j];
        const float4* w4 = (const float4*)(wg + (size_t)j * 8);
        float4 w0 = w4[0], w1 = w4[1];
        p[0] += xv * w0.x; p[1] += xv * w0.y; p[2] += xv * w0.z; p[3] += xv * w0.w;
        p[4] += xv * w1.x; p[5] += xv * w1.y; p[6] += xv * w1.z; p[7] += xv * w1.w;
    }
#pragma unroll
    for (int off = 16; off; off >>= 1)
#pragma unroll
        for (int i = 0; i < 8; i++) p[i] += __shfl_xor_sync(0xffffffffu, p[i], off);
    if ((t & 31) == 0)
#pragma unroll
        for (int i = 0; i < 8; i++) red[t >> 5][i] = p[i];
    __syncthreads();
    if (t == 0) {
        float lg[8];
#pragma unroll
        for (int i = 0; i < 8; i++) lg[i] = red[0][i] + red[1][i] + red[2][i] + red[3][i];
        int i0 = 0;
#pragma unroll
        for (int e = 1; e < 8; e++) if (lg[e] > lg[i0]) i0 = e;
        int i1 = -1;
#pragma unroll
        for (int e = 0; e < 8; e++) {
            if (e == i0) continue;
            if (i1 < 0 || lg[e] > lg[i1]) i1 = e;
        }
        float t1  = expf(lg[i1] - lg[i0]);     // <= 1
        float inv = 1.f / (1.f + t1);
        g_expid[2 * b]     = i0;
        g_gatev[2 * b]     = inv;
        g_expid[2 * b + 1] = i1;
        g_gatev[2 * b + 1] = t1 * inv;
    }
}

// ---------------- fused expert kernel: mma.sync conv2 ----------------
// smem layout (bytes):
//  A   [0, 46656):      324 rows x 144B stride (row: 64B bf16-hi | 64B bf16-lo | 16B pad)
//  B   [46656, 65088):  2 x (64 rows x 144B) double-buffered tap weights
//  XS  [65088, 78960):  conv1 input, 3 x 34 x 34 f32 (padded, halo 0)
//  sS2 [78960, +256) sQ2 [79216, +256) red [79472, +320)
#define A_STRIDE 144
#define B_OFF    46656
#define B_BUF    9216
#define XS_OFF   65088
#define SS2_OFF  78960
#define SQ2_OFF  79216
#define RED_OFF  79472
#define SMEM_BYTES (RED_OFF + 320)

__global__ void __launch_bounds__(256, 2) pair_kernel(
    const float* __restrict__ x,  const float* __restrict__ w1,
    const float* __restrict__ fcw, const float* __restrict__ fcb) {
    extern __shared__ __align__(128) char sb[];
    uint32_t Au = smem_u32(sb);
    uint32_t Bu = Au + B_OFF;
    float* XS   = (float*)(sb + XS_OFF);
    float* sS2  = (float*)(sb + SS2_OFF);
    float* sQ2  = (float*)(sb + SQ2_OFF);
    float* redm = (float*)(sb + RED_OFF);

    int p    = blockIdx.x;
    int b    = p >> 1;
    int e    = g_expid[p];
    int tid  = threadIdx.x;
    int lane = tid & 31;
    int w    = tid >> 5;

    // ---- phase 0: zero A region and XS; load BN2 consts ----
    for (int i = tid; i < 2916; i += 256) sts128(Au + i * 16, make_uint4(0, 0, 0, 0));
    for (int i = tid; i < 3468;  i += 256) XS[i] = 0.f;
    if (tid < 64) {
        sS2[tid] = g_gs2[e * 64 + tid];
        sQ2[tid] = g_gb2[e * 64 + tid];
    }
    __syncthreads();

    // ---- phase 1: fill XS interior; pre-stage B tap 0 ----
    const float* xb = x + (size_t)b * 3072;
    for (int i = tid; i < 3072; i += 256) {
        int c = i >> 10, r = (i >> 5) & 31, ww = i & 31;
        XS[c * 1156 + (r + 1) * 34 + (ww + 1)] = xb[i];
    }
    const uint4* w2src = (const uint4*)(g_w2bf) + (size_t)e * 9 * 512;
    {
#pragma unroll
        for (int j = 0; j < 2; j++) {
            int idx = tid + j * 256;                     // 0..511 over (oc, part)
            sts128(Bu + (uint32_t)((idx >> 3) * A_STRIDE + (idx & 7) * 16), w2src[idx]);
        }
    }

    // conv1 weights (2 output channels per thread) into packed registers
    int oc0 = (tid >> 4) << 1;
    unsigned long long wp1[27];
    {
        const float* wa = w1 + ((size_t)e * 32 + oc0) * 27;
#pragma unroll
        for (int j = 0; j < 27; j++) wp1[j] = pack2(wa[j], wa[27 + j]);
    }
    float s1a = g_gs1[e * 32 + oc0],     s1b = g_gs1[e * 32 + oc0 + 1];
    float q1a = g_gb1[e * 32 + oc0],     q1b = g_gb1[e * 32 + oc0 + 1];
    __syncthreads();

    // ---- phase 2: conv1 + BN + ReLU + pool -> A rows (bf16 hi|lo) ----
    {
        int ci = tid & 15;           // pooled output column
#pragma unroll 1
        for (int i = 0; i < 16; i++) {
            int px = ci, py = i;
            unsigned long long acc1[4];
#pragma unroll
            for (int d = 0; d < 4; d++) acc1[d] = 0ULL;
#pragma unroll
            for (int c = 0; c < 3; c++) {
                const float* Pc = XS + c * 1156 + (2 * py) * 34 + (2 * px);
                float patch[16];
#pragma unroll
                for (int ty = 0; ty < 4; ty++)
#pragma unroll
                    for (int tx = 0; tx < 4; tx++)
                        patch[ty * 4 + tx] = Pc[ty * 34 + tx];
#pragma unroll
                for (int d = 0; d < 4; d++) {
                    int dy = d >> 1, dx = d & 1;
#pragma unroll
                    for (int ky = 0; ky < 3; ky++)
#pragma unroll
                        for (int kx = 0; kx < 3; kx++) {
                            float a = patch[(dy + ky) * 4 + (dx + kx)];
                            ffma2(acc1[d], pack2(a, a), wp1[c * 9 + ky * 3 + kx]);
                        }
                }
            }
            float m0 = 0.f, m1 = 0.f;
#pragma unroll
            for (int d = 0; d < 4; d++) {
                float2 v = unpack2(acc1[d]);
                m0 = fmaxf(m0, fmaxf(0.f, v.x * s1a + q1a));
                m1 = fmaxf(m1, fmaxf(0.f, v.y * s1b + q1b));
            }
            __nv_bfloat16 h0 = __float2bfloat16(m0);
            __nv_bfloat16 h1 = __float2bfloat16(m1);
            __nv_bfloat16 l0 = __float2bfloat16(m0 - __bfloat162float(h0));
            __nv_bfloat16 l1 = __float2bfloat16(m1 - __bfloat162float(h1));
            uint32_t hi = ((uint32_t)__bfloat16_as_ushort(h1) << 16) | __bfloat16_as_ushort(h0);
            uint32_t lo = ((uint32_t)__bfloat16_as_ushort(l1) << 16) | __bfloat16_as_ushort(l0);
            int s = (py + 1) * 18 + (px + 1);
            sts32(Au + (uint32_t)(s * A_STRIDE + 2 * oc0), hi);
            sts32(Au + (uint32_t)(s * A_STRIDE + 64 + 2 * oc0), lo);
        }
    }
    __syncthreads();

    // ---- phase 3: 9 taps of mma.sync (per warp: M=32, N=64, K=32, 3 split terms) ----
    int xl   = lane & 15;
    int colh = lane >> 4;
    uint32_t b_lane = (uint32_t)((((lane >> 4) * 8 + (lane & 7)) * A_STRIDE) + ((lane >> 3) & 1) * 16);

    float acc[2][8][4];
#pragma unroll
    for (int mt = 0; mt < 2; mt++)
#pragma unroll
        for (int nt = 0; nt < 8; nt++)
#pragma unroll
            for (int j = 0; j < 4; j++) acc[mt][nt][j] = 0.f;

#pragma unroll 1
    for (int tap = 0; tap < 9; tap++) {
        uint32_t Bc = Bu + (uint32_t)((tap & 1) * B_BUF);
        uint4 stg0, stg1;
        if (tap < 8) {
            const uint4* sn = w2src + (size_t)(tap + 1) * 512;
            stg0 = sn[tid];
            stg1 = sn[tid + 256];
        }
        int ky = tap / 3, kx = tap % 3;
        uint32_t arow0 = Au + (uint32_t)((((2 * w + ky) * 18) + xl + kx) * A_STRIDE + colh * 16);
        uint32_t arow1 = arow0 + 18 * A_STRIDE;

#pragma unroll
        for (int kc = 0; kc < 2; kc++) {
            uint32_t ko = kc * 32;
            uint32_t ahi0[4], ahi1[4], alo0[4], alo1[4];
            ldm4(ahi0, arow0 + ko);
            ldm4(ahi1, arow1 + ko);
            ldm4(alo0, arow0 + ko + 64);
            ldm4(alo1, arow1 + ko + 64);

            uint32_t bf[8][2];
#pragma unroll
            for (int g = 0; g < 4; g++) {
                uint32_t r[4];
                ldm4(r, Bc + b_lane + (uint32_t)(g * 16 * A_STRIDE) + ko);
                bf[g * 2][0] = r[0]; bf[g * 2][1] = r[1];
                bf[g * 2 + 1][0] = r[2]; bf[g * 2 + 1][1] = r[3];
            }
#pragma unroll
            for (int nt = 0; nt < 8; nt++) {
                mma16816(acc[0][nt], ahi0, bf[nt]);
                mma16816(acc[1][nt], ahi1, bf[nt]);
                mma16816(acc[0][nt], alo0, bf[nt]);
                mma16816(acc[1][nt], alo1, bf[nt]);
            }
#pragma unroll
            for (int g = 0; g < 4; g++) {
                uint32_t r[4];
                ldm4(r, Bc + b_lane + (uint32_t)(g * 16 * A_STRIDE) + ko + 64);
                bf[g * 2][0] = r[0]; bf[g * 2][1] = r[1];
                bf[g * 2 + 1][0] = r[2]; bf[g * 2 + 1][1] = r[3];
            }
#pragma unroll
            for (int nt = 0; nt < 8; nt++) {
                mma16816(acc[0][nt], ahi0, bf[nt]);
                mma16816(acc[1][nt], ahi1, bf[nt]);
            }
        }

        if (tap < 8) {
            uint32_t Bn = Bu + (uint32_t)(((tap + 1) & 1) * B_BUF);
            sts128(Bn + (uint32_t)((tid >> 3) * A_STRIDE + (tid & 7) * 16), stg0);
            sts128(Bn + (uint32_t)(((tid >> 3) + 32) * A_STRIDE + (tid & 7) * 16), stg1);
        }
        __syncthreads();
    }

    // ---- phase 4: BN + ReLU + 2x2 pool (warp-local) + fc partials ----
    const float* fe = fcw + (size_t)e * 40960;
    float fca[10];
#pragma unroll
    for (int o = 0; o < 10; o++) fca[o] = 0.f;

    int c0b  = 2 * (lane & 3);
    bool act = ((lane >> 2) & 1) == 0;
    int pos0 = w * 8 + (lane >> 3);       // pooled flat pos (py=w, px=lane>>3)
    int pos1 = pos0 + 4;

#pragma unroll
    for (int nt = 0; nt < 8; nt++) {
        int c0 = nt * 8 + c0b, c1 = c0 + 1;
        float s0 = sS2[c0], s1 = sS2[c1], q0 = sQ2[c0], q1 = sQ2[c1];
        float v0 = fmaxf(fmaxf(0.f, acc[0][nt][0] * s0 + q0), fmaxf(0.f, acc[1][nt][0] * s0 + q0));
        float v1 = fmaxf(fmaxf(0.f, acc[0][nt][1] * s1 + q1), fmaxf(0.f, acc[1][nt][1] * s1 + q1));
        float v2 = fmaxf(fmaxf(0.f, acc[0][nt][2] * s0 + q0), fmaxf(0.f, acc[1][nt][2] * s0 + q0));
        float v3 = fmaxf(fmaxf(0.f, acc[0][nt][3] * s1 + q1), fmaxf(0.f, acc[1][nt][3] * s1 + q1));
        v0 = fmaxf(v0, __shfl_xor_sync(0xffffffffu, v0, 4));
        v1 = fmaxf(v1, __shfl_xor_sync(0xffffffffu, v1, 4));
        v2 = fmaxf(v2, __shfl_xor_sync(0xffffffffu, v2, 4));
        v3 = fmaxf(v3, __shfl_xor_sync(0xffffffffu, v3, 4));
        if (act) {
#pragma unroll
            for (int o = 0; o < 10; o++)
                fca[o] += v0 * fe[o * 4096 + c0 * 64 + pos0] + v1 * fe[o * 4096 + c1 * 64 + pos0]
                        + v2 * fe[o * 4096 + c0 * 64 + pos1] + v3 * fe[o * 4096 + c1 * 64 + pos1];
        }
    }

    // ---- phase 5: reduce fc partials, write pair output ----
#pragma unroll
    for (int o = 0; o < 10; o++)
#pragma unroll
        for (int off = 16; off; off >>= 1)
            fca[o] += __shfl_xor_sync(0xffffffffu, fca[o], off);

    if (lane == 0)
#pragma unroll
        for (int o = 0; o < 10; o++) redm[w * 10 + o] = fca[o];
    __syncthreads();
    if (tid < 10) {
        float s = 0.f;
#pragma unroll
        for (int ww = 0; ww < 8; ww++) s += redm[ww * 10 + tid];
        g_pout[p * 10 + tid] = s + fcb[e * 10 + tid];
    }
}

// ---------------- combine: y = log(g0*exp(o0) + g1*exp(o1)) ----------------
__global__ void combine_kernel(float* __restrict__ out) {
    int idx = blockIdx.x * blockDim.x + threadIdx.x;
    if (idx >= BATCH * 10) return;
    int b = idx / 10, o = idx - b * 10;
    float g0 = g_gatev[2 * b], g1 = g_gatev[2 * b + 1];
    float c = g0 * expf(g_pout[(2 * b) * 10 + o]) + g1 * expf(g_pout[(2 * b + 1) * 10 + o]);
    if (c == 0.f) c = 2.2204460492503131e-16f;   // np.finfo(float).eps
    out[idx] = logf(c);
}

// ---------------- loss: CV^2(importance) + CV^2(load), deterministic ----------------
__global__ void loss_kernel(float* __restrict__ out, int out_size) {
    __shared__ float rimp[8 * 8];
    __shared__ float rcnt[8 * 8];
    int t = threadIdx.x;   // 256
    float imp[8], cnt[8];
#pragma unroll
    for (int i = 0; i < 8; i++) { imp[i] = 0.f; cnt[i] = 0.f; }
    for (int p = t; p < 2 * BATCH; p += 256) {
        int e = g_expid[p];
        imp[e] += g_gatev[p];
        cnt[e] += 1.f;
    }
#pragma unroll
    for (int off = 16; off; off >>= 1)
#pragma unroll
        for (int i = 0; i < 8; i++) {
            imp[i] += __shfl_xor_sync(0xffffffffu, imp[i], off);
            cnt[i] += __shfl_xor_sync(0xffffffffu, cnt[i], off);
        }
    if ((t & 31) == 0)
#pragma unroll
        for (int i = 0; i < 8; i++) {
            rimp[(t >> 5) * 8 + i] = imp[i];
            rcnt[(t >> 5) * 8 + i] = cnt[i];
        }
    __syncthreads();
    if (t == 0) {
        double si = 0, sl = 0, si2 = 0, sl2 = 0;
        for (int e = 0; e < 8; e++) {
            double vi = 0, vl = 0;
            for (int w = 0; w < 8; w++) { vi += rimp[w * 8 + e]; vl += rcnt[w * 8 + e]; }
            si += vi; sl += vl; si2 += vi * vi; sl2 += vl * vl;
        }
        double mi = si / 8.0, ml = sl / 8.0;
        double vari = (si2 - 8.0 * mi * mi) / 7.0;   // ddof=1
        double varl = (sl2 - 8.0 * ml * ml) / 7.0;
        double loss = (vari / (mi * mi + 1e-10) + varl / (ml * ml + 1e-10)) * 0.01;
        out[out_size - 1] = (float)loss;
    }
}

// ---------------- launch ----------------
extern "C" void kernel_launch(void* const* d_in, const int* in_sizes, int n_in,
                              void* d_out, int out_size) {
    const float* x   = (const float*)d_in[0];
    // d_in[1] = index (unused by reference math)
    const float* wg  = (const float*)d_in[2];
    const float* w1  = (const float*)d_in[3];
    const float* b1  = (const float*)d_in[4];
    const float* g1  = (const float*)d_in[5];
    const float* be1 = (const float*)d_in[6];
    const float* rm1 = (const float*)d_in[7];
    const float* rv1 = (const float*)d_in[8];
    const float* w2  = (const float*)d_in[9];
    const float* b2  = (const float*)d_in[10];
    const float* g2  = (const float*)d_in[11];
    const float* be2 = (const float*)d_in[12];
    const float* rm2 = (const float*)d_in[13];
    const float* rv2 = (const float*)d_in[14];
    const float* fcw = (const float*)d_in[15];
    const float* fcb = (const float*)d_in[16];
    float* out = (float*)d_out;

    cudaFuncSetAttribute(pair_kernel, cudaFuncAttributeMaxDynamicSharedMemorySize, SMEM_BYTES);

    eff_kernel<<<1, 512>>>(b1, g1, be1, rm1, rv1, b2, g2, be2, rm2, rv2);
    w2bf_kernel<<<576, 256>>>(w2);
    gate_kernel<<<BATCH, 128>>>(x, wg);
    pair_kernel<<<2 * BATCH, 256, SMEM_BYTES>>>(x, w1, fcw, fcb);
    combine_kernel<<<(BATCH * 10 + 255) / 256, 256>>>(out);
    loss_kernel<<<1, 256>>>(out, out_size);
}

// round 7
// speedup vs baseline: 2.5117x; 1.2477x over previous
#include <cuda_runtime.h>
#include <cuda_fp16.h>
#include <cstdint>

#define NEXP  8
#define BATCH 4096

// ---------------- device scratch (no allocations allowed) ----------------
__device__ float g_gs1[NEXP * 32];
__device__ float g_gb1[NEXP * 32];
__device__ float g_gs2[NEXP * 64];
__device__ float g_gb2[NEXP * 64];
__device__ int   g_expid[2 * BATCH];
__device__ float g_gatev[2 * BATCH];
__device__ float g_pout[2 * BATCH * 10];
// W2 in fp16, tap-major: [e][tap][oc][ic0..31]
__device__ __half g_w2h[NEXP * 9 * 64 * 32];

// ---------------- f32x2 packed helpers (Blackwell) ----------------
static __device__ __forceinline__ unsigned long long pack2(float x, float y) {
    unsigned long long r;
    asm("mov.b64 %0, {%1, %2};" : "=l"(r) : "r"(__float_as_uint(x)), "r"(__float_as_uint(y)));
    return r;
}
static __device__ __forceinline__ void ffma2(unsigned long long& d, unsigned long long a, unsigned long long b) {
    asm("fma.rn.f32x2 %0, %1, %2, %0;" : "+l"(d) : "l"(a), "l"(b));
}
static __device__ __forceinline__ float2 unpack2(unsigned long long v) {
    unsigned int lo, hi;
    asm("mov.b64 {%0, %1}, %2;" : "=r"(lo), "=r"(hi) : "l"(v));
    return make_float2(__uint_as_float(lo), __uint_as_float(hi));
}

// ---------------- smem / mma helpers ----------------
static __device__ __forceinline__ uint32_t smem_u32(const void* p) {
    uint32_t a;
    asm("{ .reg .u64 t; cvta.to.shared.u64 t, %1; cvt.u32.u64 %0, t; }" : "=r"(a) : "l"(p));
    return a;
}
static __device__ __forceinline__ void sts32(uint32_t a, uint32_t v) {
    asm volatile("st.shared.b32 [%0], %1;" :: "r"(a), "r"(v) : "memory");
}
static __device__ __forceinline__ void sts128(uint32_t a, uint4 v) {
    asm volatile("st.shared.v4.b32 [%0], {%1,%2,%3,%4};" :: "r"(a), "r"(v.x), "r"(v.y), "r"(v.z), "r"(v.w) : "memory");
}
static __device__ __forceinline__ void ldm4(uint32_t* r, uint32_t addr) {
    asm volatile("ldmatrix.sync.aligned.m8n8.x4.shared.b16 {%0,%1,%2,%3}, [%4];"
                 : "=r"(r[0]), "=r"(r[1]), "=r"(r[2]), "=r"(r[3]) : "r"(addr));
}
static __device__ __forceinline__ void mma16816(float* d, const uint32_t* a, const uint32_t* b) {
    asm volatile("mma.sync.aligned.m16n8k16.row.col.f32.f16.f16.f32 "
                 "{%0,%1,%2,%3}, {%4,%5,%6,%7}, {%8,%9}, {%0,%1,%2,%3};"
                 : "+f"(d[0]), "+f"(d[1]), "+f"(d[2]), "+f"(d[3])
                 : "r"(a[0]), "r"(a[1]), "r"(a[2]), "r"(a[3]), "r"(b[0]), "r"(b[1]));
}

// ---------------- fold BN (eval mode) into scale/shift ----------------
__global__ void eff_kernel(const float* __restrict__ b1, const float* __restrict__ g1,
                           const float* __restrict__ be1, const float* __restrict__ rm1,
                           const float* __restrict__ rv1,
                           const float* __restrict__ b2, const float* __restrict__ g2,
                           const float* __restrict__ be2, const float* __restrict__ rm2,
                           const float* __restrict__ rv2) {
    int t = threadIdx.x;
    if (t < NEXP * 32) {
        float s = g1[t] / sqrtf(rv1[t] + 1e-5f);
        g_gs1[t] = s;
        g_gb1[t] = (b1[t] - rm1[t]) * s + be1[t];
    }
    if (t < NEXP * 64) {
        float s = g2[t] / sqrtf(rv2[t] + 1e-5f);
        g_gs2[t] = s;
        g_gb2[t] = (b2[t] - rm2[t]) * s + be2[t];
    }
}

// ---------------- prep: W2 -> fp16, tap-major ----------------
__global__ void w2h_kernel(const float* __restrict__ w2) {
    int idx = blockIdx.x * 256 + threadIdx.x;      // 147456 total
    if (idx >= NEXP * 9 * 64 * 32) return;
    int ic  = idx & 31;
    int oc  = (idx >> 5) & 63;
    int r   = idx >> 11;
    int tap = r % 9;
    int e   = r / 9;
    float w = w2[(((size_t)e * 64 + oc) * 32 + ic) * 9 + tap];
    g_w2h[((size_t)(e * 9 + tap) * 64 + oc) * 32 + ic] = __float2half_rn(w);
}

// ---------------- gating: logits, top-2, softmax, pair list ----------------
__global__ void gate_kernel(const float* __restrict__ x, const float* __restrict__ wg) {
    __shared__ float red[4][8];
    int b = blockIdx.x;
    int t = threadIdx.x;            // 128 threads
    const float* xb = x + (size_t)b * 3072;

    float p[8];
#pragma unroll
    for (int i = 0; i < 8; i++) p[i] = 0.f;

    for (int j = t; j < 3072; j += 128) {
        float xv = xb[j];
        const float4* w4 = (const float4*)(wg + (size_t)j * 8);
        float4 w0 = w4[0], w1 = w4[1];
        p[0] += xv * w0.x; p[1] += xv * w0.y; p[2] += xv * w0.z; p[3] += xv * w0.w;
        p[4] += xv * w1.x; p[5] += xv * w1.y; p[6] += xv * w1.z; p[7] += xv * w1.w;
    }
#pragma unroll
    for (int off = 16; off; off >>= 1)
#pragma unroll
        for (int i = 0; i < 8; i++) p[i] += __shfl_xor_sync(0xffffffffu, p[i], off);
    if ((t & 31) == 0)
#pragma unroll
        for (int i = 0; i < 8; i++) red[t >> 5][i] = p[i];
    __syncthreads();
    if (t == 0) {
        float lg[8];
#pragma unroll
        for (int i = 0; i < 8; i++) lg[i] = red[0][i] + red[1][i] + red[2][i] + red[3][i];
        int i0 = 0;
#pragma unroll
        for (int e = 1; e < 8; e++) if (lg[e] > lg[i0]) i0 = e;
        int i1 = -1;
#pragma unroll
        for (int e = 0; e < 8; e++) {
            if (e == i0) continue;
            if (i1 < 0 || lg[e] > lg[i1]) i1 = e;
        }
        float t1  = expf(lg[i1] - lg[i0]);     // <= 1
        float inv = 1.f / (1.f + t1);
        g_expid[2 * b]     = i0;
        g_gatev[2 * b]     = inv;
        g_expid[2 * b + 1] = i1;
        g_gatev[2 * b + 1] = t1 * inv;
    }
}

// ---------------- fused expert kernel: fp16 mma.sync conv2 ----------------
// smem layout (bytes):
//  A   [0, 25920):      324 rows x 80B stride (row: 64B fp16 x32ic | 16B pad)
//  B   [25920, 36160):  2 x (64 rows x 80B) double-buffered tap weights
//  XS  [36160, 50032):  conv1 input, 3 x 34 x 34 f32 (padded, halo 0)
//  sS2 [50032,+256) sQ2 [50288,+256) red [50544,+320)
#define A_STRIDE 80
#define B_OFF    25920
#define B_BUF    5120
#define XS_OFF   36160
#define SS2_OFF  50032
#define SQ2_OFF  50288
#define RED_OFF  50544
#define SMEM_BYTES (RED_OFF + 320)

__global__ void __launch_bounds__(256, 2) pair_kernel(
    const float* __restrict__ x,  const float* __restrict__ w1,
    const float* __restrict__ fcw, const float* __restrict__ fcb) {
    extern __shared__ __align__(128) char sb[];
    uint32_t Au = smem_u32(sb);
    uint32_t Bu = Au + B_OFF;
    float* XS   = (float*)(sb + XS_OFF);
    float* sS2  = (float*)(sb + SS2_OFF);
    float* sQ2  = (float*)(sb + SQ2_OFF);
    float* redm = (float*)(sb + RED_OFF);

    int p    = blockIdx.x;
    int b    = p >> 1;
    int e    = g_expid[p];
    int tid  = threadIdx.x;
    int lane = tid & 31;
    int w    = tid >> 5;

    // ---- phase 0: zero A region and XS; load BN2 consts ----
    for (int i = tid; i < 1620; i += 256) sts128(Au + i * 16, make_uint4(0, 0, 0, 0));
    for (int i = tid; i < 3468;  i += 256) XS[i] = 0.f;
    if (tid < 64) {
        sS2[tid] = g_gs2[e * 64 + tid];
        sQ2[tid] = g_gb2[e * 64 + tid];
    }
    __syncthreads();

    // ---- phase 1: fill XS interior; pre-stage B tap 0 ----
    const float* xb = x + (size_t)b * 3072;
    for (int i = tid; i < 3072; i += 256) {
        int c = i >> 10, r = (i >> 5) & 31, ww = i & 31;
        XS[c * 1156 + (r + 1) * 34 + (ww + 1)] = xb[i];
    }
    const uint4* w2src = (const uint4*)(g_w2h) + (size_t)e * 9 * 256;
    sts128(Bu + (uint32_t)((tid >> 2) * A_STRIDE + (tid & 3) * 16), w2src[tid]);

    // conv1 weights (2 output channels per thread) into packed registers
    int oc0 = (tid >> 4) << 1;
    unsigned long long wp1[27];
    {
        const float* wa = w1 + ((size_t)e * 32 + oc0) * 27;
#pragma unroll
        for (int j = 0; j < 27; j++) wp1[j] = pack2(wa[j], wa[27 + j]);
    }
    float s1a = g_gs1[e * 32 + oc0],     s1b = g_gs1[e * 32 + oc0 + 1];
    float q1a = g_gb1[e * 32 + oc0],     q1b = g_gb1[e * 32 + oc0 + 1];
    __syncthreads();

    // ---- phase 2: conv1 + BN + ReLU + pool -> A rows (fp16) ----
    {
        int ci = tid & 15;           // pooled output column
#pragma unroll 1
        for (int i = 0; i < 16; i++) {
            int px = ci, py = i;
            unsigned long long acc1[4];
#pragma unroll
            for (int d = 0; d < 4; d++) acc1[d] = 0ULL;
#pragma unroll
            for (int c = 0; c < 3; c++) {
                const float2* Pc2 = (const float2*)(XS + c * 1156 + (2 * py) * 34 + (2 * px));
                float patch[16];
#pragma unroll
                for (int ty = 0; ty < 4; ty++) {
                    float2 u = Pc2[ty * 17];
                    float2 v = Pc2[ty * 17 + 1];
                    patch[ty * 4 + 0] = u.x; patch[ty * 4 + 1] = u.y;
                    patch[ty * 4 + 2] = v.x; patch[ty * 4 + 3] = v.y;
                }
#pragma unroll
                for (int d = 0; d < 4; d++) {
                    int dy = d >> 1, dx = d & 1;
#pragma unroll
                    for (int ky = 0; ky < 3; ky++)
#pragma unroll
                        for (int kx = 0; kx < 3; kx++) {
                            float a = patch[(dy + ky) * 4 + (dx + kx)];
                            ffma2(acc1[d], pack2(a, a), wp1[c * 9 + ky * 3 + kx]);
                        }
                }
            }
            float m0 = 0.f, m1 = 0.f;
#pragma unroll
            for (int d = 0; d < 4; d++) {
                float2 v = unpack2(acc1[d]);
                m0 = fmaxf(m0, fmaxf(0.f, v.x * s1a + q1a));
                m1 = fmaxf(m1, fmaxf(0.f, v.y * s1b + q1b));
            }
            uint32_t hp = ((uint32_t)__half_as_ushort(__float2half_rn(m1)) << 16)
                        | __half_as_ushort(__float2half_rn(m0));
            int s = (py + 1) * 18 + (px + 1);
            sts32(Au + (uint32_t)(s * A_STRIDE + 2 * oc0), hp);
        }
    }
    __syncthreads();

    // ---- phase 3: 9 taps of fp16 mma.sync (per warp: M=32, N=64, K=32) ----
    int xl   = lane & 15;
    int colh = lane >> 4;
    uint32_t b_lane = (uint32_t)((((lane >> 4) * 8 + (lane & 7)) * A_STRIDE) + ((lane >> 3) & 1) * 16);

    float acc[2][8][4];
#pragma unroll
    for (int mt = 0; mt < 2; mt++)
#pragma unroll
        for (int nt = 0; nt < 8; nt++)
#pragma unroll
            for (int j = 0; j < 4; j++) acc[mt][nt][j] = 0.f;

#pragma unroll 1
    for (int tap = 0; tap < 9; tap++) {
        uint32_t Bc = Bu + (uint32_t)((tap & 1) * B_BUF);
        uint4 stg;
        if (tap < 8) stg = w2src[(tap + 1) * 256 + tid];

        int ky = tap / 3, kx = tap % 3;
        uint32_t arow0 = Au + (uint32_t)((((2 * w + ky) * 18) + xl + kx) * A_STRIDE + colh * 16);
        uint32_t arow1 = arow0 + 18 * A_STRIDE;

#pragma unroll
        for (int kc = 0; kc < 2; kc++) {
            uint32_t ko = kc * 32;
            uint32_t a0[4], a1[4];
            ldm4(a0, arow0 + ko);
            ldm4(a1, arow1 + ko);

            uint32_t bf[8][2];
#pragma unroll
            for (int g = 0; g < 4; g++) {
                uint32_t r[4];
                ldm4(r, Bc + b_lane + (uint32_t)(g * 16 * A_STRIDE) + ko);
                bf[g * 2][0] = r[0]; bf[g * 2][1] = r[1];
                bf[g * 2 + 1][0] = r[2]; bf[g * 2 + 1][1] = r[3];
            }
#pragma unroll
            for (int nt = 0; nt < 8; nt++) {
                mma16816(acc[0][nt], a0, bf[nt]);
                mma16816(acc[1][nt], a1, bf[nt]);
            }
        }

        if (tap < 8) {
            uint32_t Bn = Bu + (uint32_t)(((tap + 1) & 1) * B_BUF);
            sts128(Bn + (uint32_t)((tid >> 2) * A_STRIDE + (tid & 3) * 16), stg);
        }
        __syncthreads();
    }

    // ---- phase 4: BN + ReLU + 2x2 pool (warp-local) + fc partials ----
    const float* fe = fcw + (size_t)e * 40960;
    float fca[10];
#pragma unroll
    for (int o = 0; o < 10; o++) fca[o] = 0.f;

    int c0b  = 2 * (lane & 3);
    bool act = ((lane >> 2) & 1) == 0;
    int pos0 = w * 8 + (lane >> 3);       // pooled flat pos (py=w, px=lane>>3)
    int pos1 = pos0 + 4;

#pragma unroll
    for (int nt = 0; nt < 8; nt++) {
        int c0 = nt * 8 + c0b, c1 = c0 + 1;
        float s0 = sS2[c0], s1 = sS2[c1], q0 = sQ2[c0], q1 = sQ2[c1];
        float v0 = fmaxf(fmaxf(0.f, acc[0][nt][0] * s0 + q0), fmaxf(0.f, acc[1][nt][0] * s0 + q0));
        float v1 = fmaxf(fmaxf(0.f, acc[0][nt][1] * s1 + q1), fmaxf(0.f, acc[1][nt][1] * s1 + q1));
        float v2 = fmaxf(fmaxf(0.f, acc[0][nt][2] * s0 + q0), fmaxf(0.f, acc[1][nt][2] * s0 + q0));
        float v3 = fmaxf(fmaxf(0.f, acc[0][nt][3] * s1 + q1), fmaxf(0.f, acc[1][nt][3] * s1 + q1));
        v0 = fmaxf(v0, __shfl_xor_sync(0xffffffffu, v0, 4));
        v1 = fmaxf(v1, __shfl_xor_sync(0xffffffffu, v1, 4));
        v2 = fmaxf(v2, __shfl_xor_sync(0xffffffffu, v2, 4));
        v3 = fmaxf(v3, __shfl_xor_sync(0xffffffffu, v3, 4));
        if (act) {
#pragma unroll
            for (int o = 0; o < 10; o++)
                fca[o] += v0 * fe[o * 4096 + c0 * 64 + pos0] + v1 * fe[o * 4096 + c1 * 64 + pos0]
                        + v2 * fe[o * 4096 + c0 * 64 + pos1] + v3 * fe[o * 4096 + c1 * 64 + pos1];
        }
    }

    // ---- phase 5: reduce fc partials, write pair output ----
#pragma unroll
    for (int o = 0; o < 10; o++)
#pragma unroll
        for (int off = 16; off; off >>= 1)
            fca[o] += __shfl_xor_sync(0xffffffffu, fca[o], off);

    if (lane == 0)
#pragma unroll
        for (int o = 0; o < 10; o++) redm[w * 10 + o] = fca[o];
    __syncthreads();
    if (tid < 10) {
        float s = 0.f;
#pragma unroll
        for (int ww = 0; ww < 8; ww++) s += redm[ww * 10 + tid];
        g_pout[p * 10 + tid] = s + fcb[e * 10 + tid];
    }
}

// ---------------- combine: y = log(g0*exp(o0) + g1*exp(o1)) ----------------
__global__ void combine_kernel(float* __restrict__ out) {
    int idx = blockIdx.x * blockDim.x + threadIdx.x;
    if (idx >= BATCH * 10) return;
    int b = idx / 10, o = idx - b * 10;
    float g0 = g_gatev[2 * b], g1 = g_gatev[2 * b + 1];
    float c = g0 * expf(g_pout[(2 * b) * 10 + o]) + g1 * expf(g_pout[(2 * b + 1) * 10 + o]);
    if (c == 0.f) c = 2.2204460492503131e-16f;   // np.finfo(float).eps
    out[idx] = logf(c);
}

// ---------------- loss: CV^2(importance) + CV^2(load), deterministic ----------------
__global__ void loss_kernel(float* __restrict__ out, int out_size) {
    __shared__ float rimp[8 * 8];
    __shared__ float rcnt[8 * 8];
    int t = threadIdx.x;   // 256
    float imp[8], cnt[8];
#pragma unroll
    for (int i = 0; i < 8; i++) { imp[i] = 0.f; cnt[i] = 0.f; }
    for (int p = t; p < 2 * BATCH; p += 256) {
        int e = g_expid[p];
        imp[e] += g_gatev[p];
        cnt[e] += 1.f;
    }
#pragma unroll
    for (int off = 16; off; off >>= 1)
#pragma unroll
        for (int i = 0; i < 8; i++) {
            imp[i] += __shfl_xor_sync(0xffffffffu, imp[i], off);
            cnt[i] += __shfl_xor_sync(0xffffffffu, cnt[i], off);
        }
    if ((t & 31) == 0)
#pragma unroll
        for (int i = 0; i < 8; i++) {
            rimp[(t >> 5) * 8 + i] = imp[i];
            rcnt[(t >> 5) * 8 + i] = cnt[i];
        }
    __syncthreads();
    if (t == 0) {
        double si = 0, sl = 0, si2 = 0, sl2 = 0;
        for (int e = 0; e < 8; e++) {
            double vi = 0, vl = 0;
            for (int w = 0; w < 8; w++) { vi += rimp[w * 8 + e]; vl += rcnt[w * 8 + e]; }
            si += vi; sl += vl; si2 += vi * vi; sl2 += vl * vl;
        }
        double mi = si / 8.0, ml = sl / 8.0;
        double vari = (si2 - 8.0 * mi * mi) / 7.0;   // ddof=1
        double varl = (sl2 - 8.0 * ml * ml) / 7.0;
        double loss = (vari / (mi * mi + 1e-10) + varl / (ml * ml + 1e-10)) * 0.01;
        out[out_size - 1] = (float)loss;
    }
}

// ---------------- launch ----------------
extern "C" void kernel_launch(void* const* d_in, const int* in_sizes, int n_in,
                              void* d_out, int out_size) {
    const float* x   = (const float*)d_in[0];
    // d_in[1] = index (unused by reference math)
    const float* wg  = (const float*)d_in[2];
    const float* w1  = (const float*)d_in[3];
    const float* b1  = (const float*)d_in[4];
    const float* g1  = (const float*)d_in[5];
    const float* be1 = (const float*)d_in[6];
    const float* rm1 = (const float*)d_in[7];
    const float* rv1 = (const float*)d_in[8];
    const float* w2  = (const float*)d_in[9];
    const float* b2  = (const float*)d_in[10];
    const float* g2  = (const float*)d_in[11];
    const float* be2 = (const float*)d_in[12];
    const float* rm2 = (const float*)d_in[13];
    const float* rv2 = (const float*)d_in[14];
    const float* fcw = (const float*)d_in[15];
    const float* fcb = (const float*)d_in[16];
    float* out = (float*)d_out;

    cudaFuncSetAttribute(pair_kernel, cudaFuncAttributeMaxDynamicSharedMemorySize, SMEM_BYTES);

    eff_kernel<<<1, 512>>>(b1, g1, be1, rm1, rv1, b2, g2, be2, rm2, rv2);
    w2h_kernel<<<576, 256>>>(w2);
    gate_kernel<<<BATCH, 128>>>(x, wg);
    pair_kernel<<<2 * BATCH, 256, SMEM_BYTES>>>(x, w1, fcw, fcb);
    combine_kernel<<<(BATCH * 10 + 255) / 256, 256>>>(out);
    loss_kernel<<<1, 256>>>(out, out_size);
}

// round 8
// speedup vs baseline: 3.4121x; 1.3585x over previous
#include <cuda_runtime.h>
#include <cuda_fp16.h>
#include <cstdint>

#define NEXP  8
#define BATCH 4096

// ---------------- device scratch (no allocations allowed) ----------------
__device__ float g_gs1[NEXP * 32];
__device__ float g_gb1[NEXP * 32];
__device__ float g_gs2[NEXP * 64];
__device__ float g_gb2[NEXP * 64];
__device__ int   g_expid[2 * BATCH];
__device__ float g_gatev[2 * BATCH];
__device__ float g_pout[2 * BATCH * 10];
// W2 in fp16, tap-major: [e][tap][oc][ic0..31]
__device__ __half g_w2h[NEXP * 9 * 64 * 32];

// ---------------- f32x2 packed helpers (Blackwell) ----------------
static __device__ __forceinline__ unsigned long long pack2(float x, float y) {
    unsigned long long r;
    asm("mov.b64 %0, {%1, %2};" : "=l"(r) : "r"(__float_as_uint(x)), "r"(__float_as_uint(y)));
    return r;
}
static __device__ __forceinline__ void ffma2(unsigned long long& d, unsigned long long a, unsigned long long b) {
    asm("fma.rn.f32x2 %0, %1, %2, %0;" : "+l"(d) : "l"(a), "l"(b));
}
static __device__ __forceinline__ float2 unpack2(unsigned long long v) {
    unsigned int lo, hi;
    asm("mov.b64 {%0, %1}, %2;" : "=r"(lo), "=r"(hi) : "l"(v));
    return make_float2(__uint_as_float(lo), __uint_as_float(hi));
}

// ---------------- smem / mma helpers ----------------
static __device__ __forceinline__ uint32_t smem_u32(const void* p) {
    uint32_t a;
    asm("{ .reg .u64 t; cvta.to.shared.u64 t, %1; cvt.u32.u64 %0, t; }" : "=r"(a) : "l"(p));
    return a;
}
static __device__ __forceinline__ void sts32(uint32_t a, uint32_t v) {
    asm volatile("st.shared.b32 [%0], %1;" :: "r"(a), "r"(v) : "memory");
}
static __device__ __forceinline__ void sts128(uint32_t a, uint4 v) {
    asm volatile("st.shared.v4.b32 [%0], {%1,%2,%3,%4};" :: "r"(a), "r"(v.x), "r"(v.y), "r"(v.z), "r"(v.w) : "memory");
}
static __device__ __forceinline__ void ldm4(uint32_t* r, uint32_t addr) {
    asm volatile("ldmatrix.sync.aligned.m8n8.x4.shared.b16 {%0,%1,%2,%3}, [%4];"
                 : "=r"(r[0]), "=r"(r[1]), "=r"(r[2]), "=r"(r[3]) : "r"(addr));
}
static __device__ __forceinline__ void mma16816(float* d, const uint32_t* a, const uint32_t* b) {
    asm volatile("mma.sync.aligned.m16n8k16.row.col.f32.f16.f16.f32 "
                 "{%0,%1,%2,%3}, {%4,%5,%6,%7}, {%8,%9}, {%0,%1,%2,%3};"
                 : "+f"(d[0]), "+f"(d[1]), "+f"(d[2]), "+f"(d[3])
                 : "r"(a[0]), "r"(a[1]), "r"(a[2]), "r"(a[3]), "r"(b[0]), "r"(b[1]));
}

// ---------------- fold BN (eval mode) into scale/shift ----------------
__global__ void eff_kernel(const float* __restrict__ b1, const float* __restrict__ g1,
                           const float* __restrict__ be1, const float* __restrict__ rm1,
                           const float* __restrict__ rv1,
                           const float* __restrict__ b2, const float* __restrict__ g2,
                           const float* __restrict__ be2, const float* __restrict__ rm2,
                           const float* __restrict__ rv2) {
    int t = threadIdx.x;
    if (t < NEXP * 32) {
        float s = g1[t] / sqrtf(rv1[t] + 1e-5f);
        g_gs1[t] = s;
        g_gb1[t] = (b1[t] - rm1[t]) * s + be1[t];
    }
    if (t < NEXP * 64) {
        float s = g2[t] / sqrtf(rv2[t] + 1e-5f);
        g_gs2[t] = s;
        g_gb2[t] = (b2[t] - rm2[t]) * s + be2[t];
    }
}

// ---------------- prep: W2 -> fp16, tap-major ----------------
__global__ void w2h_kernel(const float* __restrict__ w2) {
    int idx = blockIdx.x * 256 + threadIdx.x;      // 147456 total
    if (idx >= NEXP * 9 * 64 * 32) return;
    int ic  = idx & 31;
    int oc  = (idx >> 5) & 63;
    int r   = idx >> 11;
    int tap = r % 9;
    int e   = r / 9;
    float w = w2[(((size_t)e * 64 + oc) * 32 + ic) * 9 + tap];
    g_w2h[((size_t)(e * 9 + tap) * 64 + oc) * 32 + ic] = __float2half_rn(w);
}

// ---------------- gating: logits, top-2, softmax, pair list ----------------
__global__ void gate_kernel(const float* __restrict__ x, const float* __restrict__ wg) {
    __shared__ float red[4][8];
    int b = blockIdx.x;
    int t = threadIdx.x;            // 128 threads
    const float* xb = x + (size_t)b * 3072;

    float p[8];
#pragma unroll
    for (int i = 0; i < 8; i++) p[i] = 0.f;

    for (int j = t; j < 3072; j += 128) {
        float xv = xb[j];
        const float4* w4 = (const float4*)(wg + (size_t)j * 8);
        float4 w0 = w4[0], w1 = w4[1];
        p[0] += xv * w0.x; p[1] += xv * w0.y; p[2] += xv * w0.z; p[3] += xv * w0.w;
        p[4] += xv * w1.x; p[5] += xv * w1.y; p[6] += xv * w1.z; p[7] += xv * w1.w;
    }
#pragma unroll
    for (int off = 16; off; off >>= 1)
#pragma unroll
        for (int i = 0; i < 8; i++) p[i] += __shfl_xor_sync(0xffffffffu, p[i], off);
    if ((t & 31) == 0)
#pragma unroll
        for (int i = 0; i < 8; i++) red[t >> 5][i] = p[i];
    __syncthreads();
    if (t == 0) {
        float lg[8];
#pragma unroll
        for (int i = 0; i < 8; i++) lg[i] = red[0][i] + red[1][i] + red[2][i] + red[3][i];
        int i0 = 0;
#pragma unroll
        for (int e = 1; e < 8; e++) if (lg[e] > lg[i0]) i0 = e;
        int i1 = -1;
#pragma unroll
        for (int e = 0; e < 8; e++) {
            if (e == i0) continue;
            if (i1 < 0 || lg[e] > lg[i1]) i1 = e;
        }
        float t1  = expf(lg[i1] - lg[i0]);     // <= 1
        float inv = 1.f / (1.f + t1);
        g_expid[2 * b]     = i0;
        g_gatev[2 * b]     = inv;
        g_expid[2 * b + 1] = i1;
        g_gatev[2 * b + 1] = t1 * inv;
    }
}

// ---------------- fused expert kernel: fp16 mma.sync conv2 ----------------
// smem layout (bytes):
//  A   [0, 25920):      324 rows x 80B stride (row: 64B fp16 x32ic | 16B pad)
//                       reused after phase 3 as h2s[4096] f32 (16KB)
//  B   [25920, 36160):  2 x (64 rows x 80B) double-buffered tap weights
//  XS  [36160, 50032):  conv1 input, 3 x 34 x 34 f32 (padded, halo 0)
//  sS2 [50032,+256) sQ2 [50288,+256) red [50544,+320)
#define A_STRIDE 80
#define B_OFF    25920
#define B_BUF    5120
#define XS_OFF   36160
#define SS2_OFF  50032
#define SQ2_OFF  50288
#define RED_OFF  50544
#define SMEM_BYTES (RED_OFF + 320)

__global__ void __launch_bounds__(256, 2) pair_kernel(
    const float* __restrict__ x,  const float* __restrict__ w1,
    const float* __restrict__ fcw, const float* __restrict__ fcb) {
    extern __shared__ __align__(128) char sb[];
    uint32_t Au = smem_u32(sb);
    uint32_t Bu = Au + B_OFF;
    float* XS   = (float*)(sb + XS_OFF);
    float* sS2  = (float*)(sb + SS2_OFF);
    float* sQ2  = (float*)(sb + SQ2_OFF);
    float* redm = (float*)(sb + RED_OFF);
    float* h2s  = (float*)sb;                     // overlays A after phase 3

    int p    = blockIdx.x;
    int b    = p >> 1;
    int e    = g_expid[p];
    int tid  = threadIdx.x;
    int lane = tid & 31;
    int w    = tid >> 5;

    // ---- phase 0: zero A region and XS; load BN2 consts ----
    for (int i = tid; i < 1620; i += 256) sts128(Au + i * 16, make_uint4(0, 0, 0, 0));
    for (int i = tid; i < 3468;  i += 256) XS[i] = 0.f;
    if (tid < 64) {
        sS2[tid] = g_gs2[e * 64 + tid];
        sQ2[tid] = g_gb2[e * 64 + tid];
    }
    __syncthreads();

    // ---- phase 1: fill XS interior; pre-stage B tap 0 ----
    const float* xb = x + (size_t)b * 3072;
    for (int i = tid; i < 3072; i += 256) {
        int c = i >> 10, r = (i >> 5) & 31, ww = i & 31;
        XS[c * 1156 + (r + 1) * 34 + (ww + 1)] = xb[i];
    }
    const uint4* w2src = (const uint4*)(g_w2h) + (size_t)e * 9 * 256;
    sts128(Bu + (uint32_t)((tid >> 2) * A_STRIDE + (tid & 3) * 16), w2src[tid]);

    // conv1 weights (2 output channels per thread) into packed registers
    int oc0 = (tid >> 4) << 1;
    unsigned long long wp1[27];
    {
        const float* wa = w1 + ((size_t)e * 32 + oc0) * 27;
#pragma unroll
        for (int j = 0; j < 27; j++) wp1[j] = pack2(wa[j], wa[27 + j]);
    }
    float s1a = g_gs1[e * 32 + oc0],     s1b = g_gs1[e * 32 + oc0 + 1];
    float q1a = g_gb1[e * 32 + oc0],     q1b = g_gb1[e * 32 + oc0 + 1];
    __syncthreads();

    // ---- phase 2: conv1 + BN + ReLU + pool -> A rows (fp16) ----
    // Two pooled rows (py=2i, 2i+1) per iteration share a 6-row input window:
    // patch LDS drops from 16 to 12 LDS.64 per channel per row-pair.
    {
        int ci = tid & 15;           // pooled output column (px)
#pragma unroll 1
        for (int i = 0; i < 8; i++) {
            unsigned long long acc1[2][4];
#pragma unroll
            for (int h = 0; h < 2; h++)
#pragma unroll
                for (int d = 0; d < 4; d++) acc1[h][d] = 0ULL;
#pragma unroll
            for (int c = 0; c < 3; c++) {
                const float2* Pc2 = (const float2*)(XS + c * 1156 + (4 * i) * 34 + 2 * ci);
                float rw[6][4];
#pragma unroll
                for (int r = 0; r < 6; r++) {
                    float2 u = Pc2[r * 17];
                    float2 v = Pc2[r * 17 + 1];
                    rw[r][0] = u.x; rw[r][1] = u.y; rw[r][2] = v.x; rw[r][3] = v.y;
                }
#pragma unroll
                for (int h = 0; h < 2; h++)
#pragma unroll
                    for (int d = 0; d < 4; d++) {
                        int dy = d >> 1, dx = d & 1;
#pragma unroll
                        for (int ky = 0; ky < 3; ky++)
#pragma unroll
                            for (int kx = 0; kx < 3; kx++) {
                                float a = rw[2 * h + dy + ky][dx + kx];
                                ffma2(acc1[h][d], pack2(a, a), wp1[c * 9 + ky * 3 + kx]);
                            }
                    }
            }
#pragma unroll
            for (int h = 0; h < 2; h++) {
                float m0 = 0.f, m1 = 0.f;
#pragma unroll
                for (int d = 0; d < 4; d++) {
                    float2 v = unpack2(acc1[h][d]);
                    m0 = fmaxf(m0, fmaxf(0.f, v.x * s1a + q1a));
                    m1 = fmaxf(m1, fmaxf(0.f, v.y * s1b + q1b));
                }
                uint32_t hp = ((uint32_t)__half_as_ushort(__float2half_rn(m1)) << 16)
                            | __half_as_ushort(__float2half_rn(m0));
                int s = (2 * i + h + 1) * 18 + (ci + 1);
                sts32(Au + (uint32_t)(s * A_STRIDE + 2 * oc0), hp);
            }
        }
    }
    __syncthreads();

    // ---- phase 3: 9 taps of fp16 mma.sync (per warp: M=32, N=64, K=32) ----
    int xl   = lane & 15;
    int colh = lane >> 4;
    uint32_t b_lane = (uint32_t)((((lane >> 4) * 8 + (lane & 7)) * A_STRIDE) + ((lane >> 3) & 1) * 16);

    float acc[2][8][4];
#pragma unroll
    for (int mt = 0; mt < 2; mt++)
#pragma unroll
        for (int nt = 0; nt < 8; nt++)
#pragma unroll
            for (int j = 0; j < 4; j++) acc[mt][nt][j] = 0.f;

#pragma unroll 1
    for (int tap = 0; tap < 9; tap++) {
        uint32_t Bc = Bu + (uint32_t)((tap & 1) * B_BUF);
        uint4 stg;
        if (tap < 8) stg = w2src[(tap + 1) * 256 + tid];

        int ky = tap / 3, kx = tap % 3;
        uint32_t arow0 = Au + (uint32_t)((((2 * w + ky) * 18) + xl + kx) * A_STRIDE + colh * 16);
        uint32_t arow1 = arow0 + 18 * A_STRIDE;

#pragma unroll
        for (int kc = 0; kc < 2; kc++) {
            uint32_t ko = kc * 32;
            uint32_t a0[4], a1[4];
            ldm4(a0, arow0 + ko);
            ldm4(a1, arow1 + ko);

            uint32_t bf[8][2];
#pragma unroll
            for (int g = 0; g < 4; g++) {
                uint32_t r[4];
                ldm4(r, Bc + b_lane + (uint32_t)(g * 16 * A_STRIDE) + ko);
                bf[g * 2][0] = r[0]; bf[g * 2][1] = r[1];
                bf[g * 2 + 1][0] = r[2]; bf[g * 2 + 1][1] = r[3];
            }
#pragma unroll
            for (int nt = 0; nt < 8; nt++) {
                mma16816(acc[0][nt], a0, bf[nt]);
                mma16816(acc[1][nt], a1, bf[nt]);
            }
        }

        if (tap < 8) {
            uint32_t Bn = Bu + (uint32_t)(((tap + 1) & 1) * B_BUF);
            sts128(Bn + (uint32_t)((tid >> 2) * A_STRIDE + (tid & 3) * 16), stg);
        }
        __syncthreads();
    }

    // ---- phase 4: BN + ReLU + 2x2 pool (warp-local) -> h2s smem ----
    {
        int c0b  = 2 * (lane & 3);
        bool act = ((lane >> 2) & 1) == 0;
        int pos0 = w * 8 + (lane >> 3);       // pooled flat pos (py=w, px=lane>>3)
        int pos1 = pos0 + 4;
#pragma unroll
        for (int nt = 0; nt < 8; nt++) {
            int c0 = nt * 8 + c0b, c1 = c0 + 1;
            float s0 = sS2[c0], s1 = sS2[c1], q0 = sQ2[c0], q1 = sQ2[c1];
            float v0 = fmaxf(fmaxf(0.f, acc[0][nt][0] * s0 + q0), fmaxf(0.f, acc[1][nt][0] * s0 + q0));
            float v1 = fmaxf(fmaxf(0.f, acc[0][nt][1] * s1 + q1), fmaxf(0.f, acc[1][nt][1] * s1 + q1));
            float v2 = fmaxf(fmaxf(0.f, acc[0][nt][2] * s0 + q0), fmaxf(0.f, acc[1][nt][2] * s0 + q0));
            float v3 = fmaxf(fmaxf(0.f, acc[0][nt][3] * s1 + q1), fmaxf(0.f, acc[1][nt][3] * s1 + q1));
            v0 = fmaxf(v0, __shfl_xor_sync(0xffffffffu, v0, 4));
            v1 = fmaxf(v1, __shfl_xor_sync(0xffffffffu, v1, 4));
            v2 = fmaxf(v2, __shfl_xor_sync(0xffffffffu, v2, 4));
            v3 = fmaxf(v3, __shfl_xor_sync(0xffffffffu, v3, 4));
            if (act) {
                h2s[c0 * 64 + pos0] = v0;
                h2s[c1 * 64 + pos0] = v1;
                h2s[c0 * 64 + pos1] = v2;
                h2s[c1 * 64 + pos1] = v3;
            }
        }
    }
    __syncthreads();

    // ---- phase 5: coalesced fc GEMV (fe read as contiguous float4 stripes) ----
    const float4* fe4  = (const float4*)(fcw + (size_t)e * 40960);
    const float4* h2s4 = (const float4*)h2s;
    float fca[10];
#pragma unroll
    for (int o = 0; o < 10; o++) fca[o] = 0.f;
#pragma unroll
    for (int it = 0; it < 4; it++) {
        int j4 = it * 256 + tid;
        float4 h = h2s4[j4];
#pragma unroll
        for (int o = 0; o < 10; o++) {
            float4 wv = fe4[o * 1024 + j4];
            fca[o] += h.x * wv.x + h.y * wv.y + h.z * wv.z + h.w * wv.w;
        }
    }

    // ---- phase 6: reduce fc partials, write pair output ----
#pragma unroll
    for (int o = 0; o < 10; o++)
#pragma unroll
        for (int off = 16; off; off >>= 1)
            fca[o] += __shfl_xor_sync(0xffffffffu, fca[o], off);

    if (lane == 0)
#pragma unroll
        for (int o = 0; o < 10; o++) redm[w * 10 + o] = fca[o];
    __syncthreads();
    if (tid < 10) {
        float s = 0.f;
#pragma unroll
        for (int ww = 0; ww < 8; ww++) s += redm[ww * 10 + tid];
        g_pout[p * 10 + tid] = s + fcb[e * 10 + tid];
    }
}

// ---------------- combine: y = log(g0*exp(o0) + g1*exp(o1)) ----------------
__global__ void combine_kernel(float* __restrict__ out) {
    int idx = blockIdx.x * blockDim.x + threadIdx.x;
    if (idx >= BATCH * 10) return;
    int b = idx / 10, o = idx - b * 10;
    float g0 = g_gatev[2 * b], g1 = g_gatev[2 * b + 1];
    float c = g0 * expf(g_pout[(2 * b) * 10 + o]) + g1 * expf(g_pout[(2 * b + 1) * 10 + o]);
    if (c == 0.f) c = 2.2204460492503131e-16f;   // np.finfo(float).eps
    out[idx] = logf(c);
}

// ---------------- loss: CV^2(importance) + CV^2(load), deterministic ----------------
__global__ void loss_kernel(float* __restrict__ out, int out_size) {
    __shared__ float rimp[8 * 8];
    __shared__ float rcnt[8 * 8];
    int t = threadIdx.x;   // 256
    float imp[8], cnt[8];
#pragma unroll
    for (int i = 0; i < 8; i++) { imp[i] = 0.f; cnt[i] = 0.f; }
    for (int p = t; p < 2 * BATCH; p += 256) {
        int e = g_expid[p];
        imp[e] += g_gatev[p];
        cnt[e] += 1.f;
    }
#pragma unroll
    for (int off = 16; off; off >>= 1)
#pragma unroll
        for (int i = 0; i < 8; i++) {
            imp[i] += __shfl_xor_sync(0xffffffffu, imp[i], off);
            cnt[i] += __shfl_xor_sync(0xffffffffu, cnt[i], off);
        }
    if ((t & 31) == 0)
#pragma unroll
        for (int i = 0; i < 8; i++) {
            rimp[(t >> 5) * 8 + i] = imp[i];
            rcnt[(t >> 5) * 8 + i] = cnt[i];
        }
    __syncthreads();
    if (t == 0) {
        double si = 0, sl = 0, si2 = 0, sl2 = 0;
        for (int e = 0; e < 8; e++) {
            double vi = 0, vl = 0;
            for (int w = 0; w < 8; w++) { vi += rimp[w * 8 + e]; vl += rcnt[w * 8 + e]; }
            si += vi; sl += vl; si2 += vi * vi; sl2 += vl * vl;
        }
        double mi = si / 8.0, ml = sl / 8.0;
        double vari = (si2 - 8.0 * mi * mi) / 7.0;   // ddof=1
        double varl = (sl2 - 8.0 * ml * ml) / 7.0;
        double loss = (vari / (mi * mi + 1e-10) + varl / (ml * ml + 1e-10)) * 0.01;
        out[out_size - 1] = (float)loss;
    }
}

// ---------------- launch ----------------
extern "C" void kernel_launch(void* const* d_in, const int* in_sizes, int n_in,
                              void* d_out, int out_size) {
    const float* x   = (const float*)d_in[0];
    // d_in[1] = index (unused by reference math)
    const float* wg  = (const float*)d_in[2];
    const float* w1  = (const float*)d_in[3];
    const float* b1  = (const float*)d_in[4];
    const float* g1  = (const float*)d_in[5];
    const float* be1 = (const float*)d_in[6];
    const float* rm1 = (const float*)d_in[7];
    const float* rv1 = (const float*)d_in[8];
    const float* w2  = (const float*)d_in[9];
    const float* b2  = (const float*)d_in[10];
    const float* g2  = (const float*)d_in[11];
    const float* be2 = (const float*)d_in[12];
    const float* rm2 = (const float*)d_in[13];
    const float* rv2 = (const float*)d_in[14];
    const float* fcw = (const float*)d_in[15];
    const float* fcb = (const float*)d_in[16];
    float* out = (float*)d_out;

    cudaFuncSetAttribute(pair_kernel, cudaFuncAttributeMaxDynamicSharedMemorySize, SMEM_BYTES);

    eff_kernel<<<1, 512>>>(b1, g1, be1, rm1, rv1, b2, g2, be2, rm2, rv2);
    w2h_kernel<<<576, 256>>>(w2);
    gate_kernel<<<BATCH, 128>>>(x, wg);
    pair_kernel<<<2 * BATCH, 256, SMEM_BYTES>>>(x, w1, fcw, fcb);
    combine_kernel<<<(BATCH * 10 + 255) / 256, 256>>>(out);
    loss_kernel<<<1, 256>>>(out, out_size);
}

// round 9
// speedup vs baseline: 4.4277x; 1.2976x over previous
#include <cuda_runtime.h>
#include <cuda_fp16.h>
#include <cstdint>

#define NEXP  8
#define BATCH 4096

// ---------------- device scratch (no allocations allowed) ----------------
__device__ float g_gs1[NEXP * 32];
__device__ float g_gb1[NEXP * 32];
__device__ float g_gs2[NEXP * 64];
__device__ float g_gb2[NEXP * 64];
__device__ int   g_expid[2 * BATCH];
__device__ float g_gatev[2 * BATCH];
__device__ float g_pout[2 * BATCH * 10];
// W2 in fp16, tap-major: [e][tap][oc64][ic0..31]
__device__ __half g_w2h[NEXP * 9 * 64 * 32];
// W1 in fp16, tap-major: [e][tap][oc32][k8: ic0..2, 0,0,0,0,0]  (zero-padded; .bss is zero-init)
__device__ __half g_w1h[NEXP * 9 * 32 * 8];

// ---------------- f32x2 packed helpers ----------------
static __device__ __forceinline__ unsigned long long pack2(float x, float y) {
    unsigned long long r;
    asm("mov.b64 %0, {%1, %2};" : "=l"(r) : "r"(__float_as_uint(x)), "r"(__float_as_uint(y)));
    return r;
}

// ---------------- smem / mma helpers ----------------
static __device__ __forceinline__ uint32_t smem_u32(const void* p) {
    uint32_t a;
    asm("{ .reg .u64 t; cvta.to.shared.u64 t, %1; cvt.u32.u64 %0, t; }" : "=r"(a) : "l"(p));
    return a;
}
static __device__ __forceinline__ void sts32(uint32_t a, uint32_t v) {
    asm volatile("st.shared.b32 [%0], %1;" :: "r"(a), "r"(v) : "memory");
}
static __device__ __forceinline__ void sts128(uint32_t a, uint4 v) {
    asm volatile("st.shared.v4.b32 [%0], {%1,%2,%3,%4};" :: "r"(a), "r"(v.x), "r"(v.y), "r"(v.z), "r"(v.w) : "memory");
}
static __device__ __forceinline__ void ldm4(uint32_t* r, uint32_t addr) {
    asm volatile("ldmatrix.sync.aligned.m8n8.x4.shared.b16 {%0,%1,%2,%3}, [%4];"
                 : "=r"(r[0]), "=r"(r[1]), "=r"(r[2]), "=r"(r[3]) : "r"(addr));
}
static __device__ __forceinline__ void mma16816(float* d, const uint32_t* a, const uint32_t* b) {
    asm volatile("mma.sync.aligned.m16n8k16.row.col.f32.f16.f16.f32 "
                 "{%0,%1,%2,%3}, {%4,%5,%6,%7}, {%8,%9}, {%0,%1,%2,%3};"
                 : "+f"(d[0]), "+f"(d[1]), "+f"(d[2]), "+f"(d[3])
                 : "r"(a[0]), "r"(a[1]), "r"(a[2]), "r"(a[3]), "r"(b[0]), "r"(b[1]));
}
static __device__ __forceinline__ void mma1688(float* d, uint32_t a0, uint32_t a1, uint32_t b0) {
    asm volatile("mma.sync.aligned.m16n8k8.row.col.f32.f16.f16.f32 "
                 "{%0,%1,%2,%3}, {%4,%5}, {%6}, {%0,%1,%2,%3};"
                 : "+f"(d[0]), "+f"(d[1]), "+f"(d[2]), "+f"(d[3])
                 : "r"(a0), "r"(a1), "r"(b0));
}
static __device__ __forceinline__ uint32_t h2pack(float a, float b) {
    return ((uint32_t)__half_as_ushort(__float2half_rn(b)) << 16)
         | (uint32_t)__half_as_ushort(__float2half_rn(a));
}

// ---------------- fold BN (eval mode) into scale/shift ----------------
__global__ void eff_kernel(const float* __restrict__ b1, const float* __restrict__ g1,
                           const float* __restrict__ be1, const float* __restrict__ rm1,
                           const float* __restrict__ rv1,
                           const float* __restrict__ b2, const float* __restrict__ g2,
                           const float* __restrict__ be2, const float* __restrict__ rm2,
                           const float* __restrict__ rv2) {
    int t = threadIdx.x;
    if (t < NEXP * 32) {
        float s = g1[t] / sqrtf(rv1[t] + 1e-5f);
        g_gs1[t] = s;
        g_gb1[t] = (b1[t] - rm1[t]) * s + be1[t];
    }
    if (t < NEXP * 64) {
        float s = g2[t] / sqrtf(rv2[t] + 1e-5f);
        g_gs2[t] = s;
        g_gb2[t] = (b2[t] - rm2[t]) * s + be2[t];
    }
}

// ---------------- prep: W2 -> fp16, tap-major ----------------
__global__ void w2h_kernel(const float* __restrict__ w2) {
    int idx = blockIdx.x * 256 + threadIdx.x;      // 147456 total
    if (idx >= NEXP * 9 * 64 * 32) return;
    int ic  = idx & 31;
    int oc  = (idx >> 5) & 63;
    int r   = idx >> 11;
    int tap = r % 9;
    int e   = r / 9;
    float w = w2[(((size_t)e * 64 + oc) * 32 + ic) * 9 + tap];
    g_w2h[((size_t)(e * 9 + tap) * 64 + oc) * 32 + ic] = __float2half_rn(w);
}

// ---------------- prep: W1 -> fp16, tap-major, k8-padded ----------------
__global__ void w1h_kernel(const float* __restrict__ w1) {
    int idx = blockIdx.x * 256 + threadIdx.x;      // 6912 total
    if (idx >= NEXP * 9 * 32 * 3) return;
    int ic  = idx % 3;
    int t   = idx / 3;
    int oc  = t % 32;  t /= 32;
    int tap = t % 9;
    int e   = t / 9;
    float v = w1[(((size_t)e * 32 + oc) * 3 + ic) * 9 + tap];
    g_w1h[((size_t)(e * 9 + tap) * 32 + oc) * 8 + ic] = __float2half_rn(v);
}

// ---------------- gating: logits, top-2, softmax, pair list ----------------
__global__ void gate_kernel(const float* __restrict__ x, const float* __restrict__ wg) {
    __shared__ float red[4][8];
    int b = blockIdx.x;
    int t = threadIdx.x;            // 128 threads
    const float* xb = x + (size_t)b * 3072;

    float p[8];
#pragma unroll
    for (int i = 0; i < 8; i++) p[i] = 0.f;

    for (int j = t; j < 3072; j += 128) {
        float xv = xb[j];
        const float4* w4 = (const float4*)(wg + (size_t)j * 8);
        float4 w0 = w4[0], w1 = w4[1];
        p[0] += xv * w0.x; p[1] += xv * w0.y; p[2] += xv * w0.z; p[3] += xv * w0.w;
        p[4] += xv * w1.x; p[5] += xv * w1.y; p[6] += xv * w1.z; p[7] += xv * w1.w;
    }
#pragma unroll
    for (int off = 16; off; off >>= 1)
#pragma unroll
        for (int i = 0; i < 8; i++) p[i] += __shfl_xor_sync(0xffffffffu, p[i], off);
    if ((t & 31) == 0)
#pragma unroll
        for (int i = 0; i < 8; i++) red[t >> 5][i] = p[i];
    __syncthreads();
    if (t == 0) {
        float lg[8];
#pragma unroll
        for (int i = 0; i < 8; i++) lg[i] = red[0][i] + red[1][i] + red[2][i] + red[3][i];
        int i0 = 0;
#pragma unroll
        for (int e = 1; e < 8; e++) if (lg[e] > lg[i0]) i0 = e;
        int i1 = -1;
#pragma unroll
        for (int e = 0; e < 8; e++) {
            if (e == i0) continue;
            if (i1 < 0 || lg[e] > lg[i1]) i1 = e;
        }
        float t1  = expf(lg[i1] - lg[i0]);     // <= 1
        float inv = 1.f / (1.f + t1);
        g_expid[2 * b]     = i0;
        g_gatev[2 * b]     = inv;
        g_expid[2 * b + 1] = i1;
        g_gatev[2 * b + 1] = t1 * inv;
    }
}

// ---------------- fused expert kernel: fp16 mma for BOTH convs ----------------
// smem layout (bytes):
//  A    [0, 25920):       324 rows x 80B (conv2 A: [s][32 oc fp16] + 16B pad)
//                         reused after phase 3 as h2s[4096] f32 (16KB)
//  B2   [25920, 72000):   9 taps x 64 rows x 80B (conv2 weights, all-resident)
//  XH   [72000, 90496):   conv1 input fp16, 34x34 grid x 16B rows [ic0..2, 0pad]
//  W1H  [90496, 95104):   9 taps x 32 rows x 16B (conv1 weights)
//  sS1  [95104,+128) sQ1 [95232,+128) sS2 [95360,+256) sQ2 [95616,+256) red [95872,+320)
#define A_STRIDE 80
#define B2_OFF   25920
#define XH_OFF   72000
#define W1H_OFF  90496
#define SS1_OFF  95104
#define SQ1_OFF  95232
#define SS2_OFF  95360
#define SQ2_OFF  95616
#define RED_OFF  95872
#define SMEM_BYTES (RED_OFF + 320)

__global__ void __launch_bounds__(256, 2) pair_kernel(
    const float* __restrict__ x,
    const float* __restrict__ fcw, const float* __restrict__ fcb) {
    extern __shared__ __align__(128) char sb[];
    uint32_t Au   = smem_u32(sb);
    uint32_t B2u  = Au + B2_OFF;
    uint32_t XHu  = Au + XH_OFF;
    uint32_t W1Hu = Au + W1H_OFF;
    float* sS1  = (float*)(sb + SS1_OFF);
    float* sQ1  = (float*)(sb + SQ1_OFF);
    float* sS2  = (float*)(sb + SS2_OFF);
    float* sQ2  = (float*)(sb + SQ2_OFF);
    float* redm = (float*)(sb + RED_OFF);
    float* h2s  = (float*)sb;                     // overlays A after phase 3

    int p    = blockIdx.x;
    int b    = p >> 1;
    int e    = g_expid[p];
    int tid  = threadIdx.x;
    int lane = tid & 31;
    int w    = tid >> 5;

    // ---- phase 0: zero A halo + XH; load BN consts ----
    for (int i = tid; i < 1620; i += 256) sts128(Au + i * 16, make_uint4(0, 0, 0, 0));
    for (int i = tid; i < 1156; i += 256) sts128(XHu + i * 16, make_uint4(0, 0, 0, 0));
    if (tid < 32) {
        sS1[tid] = g_gs1[e * 32 + tid];
        sQ1[tid] = g_gb1[e * 32 + tid];
    }
    if (tid < 64) {
        sS2[tid] = g_gs2[e * 64 + tid];
        sQ2[tid] = g_gb2[e * 64 + tid];
    }
    __syncthreads();

    // ---- phase 1: stage XH interior (x->fp16), W1H, and all 9 B2 tap tiles ----
    {
        const float* xb = x + (size_t)b * 3072;
#pragma unroll
        for (int it = 0; it < 4; it++) {
            int pp = tid + it * 256;              // position 0..1023
            float v0 = xb[pp];
            float v1 = xb[1024 + pp];
            float v2 = xb[2048 + pp];
            uint4 u;
            u.x = h2pack(v0, v1);
            u.y = (uint32_t)__half_as_ushort(__float2half_rn(v2));
            u.z = 0; u.w = 0;
            int y = pp >> 5, xx = pp & 31;
            sts128(XHu + (uint32_t)(((y + 1) * 34 + xx + 1) * 16), u);
        }
        const uint4* w1src = (const uint4*)(g_w1h) + (size_t)e * 9 * 32;   // 288 uint4
        if (tid < 288 - 256) { }  // (avoid warning path below handles)
        for (int i = tid; i < 288; i += 256)
            sts128(W1Hu + (uint32_t)(i * 16), w1src[i]);
        const uint4* w2src = (const uint4*)(g_w2h) + (size_t)e * 9 * 256;  // 2304 uint4
#pragma unroll
        for (int j = 0; j < 9; j++) {
            int i = tid + j * 256;
            sts128(B2u + (uint32_t)((i >> 2) * A_STRIDE + (i & 3) * 16), w2src[i]);
        }
    }
    __syncthreads();

    // ---- phase 2: conv1 via fp16 mma (9 taps, m16n8k8), BN+ReLU+pool -> A rows ----
    {
        float s1v[4][2], q1v[4][2];
#pragma unroll
        for (int nt = 0; nt < 4; nt++) {
            int oc0 = nt * 8 + 2 * (lane & 3);
            s1v[nt][0] = sS1[oc0];     s1v[nt][1] = sS1[oc0 + 1];
            q1v[nt][0] = sQ1[oc0];     q1v[nt][1] = sQ1[oc0 + 1];
        }
        int rr  = (lane & 7) + ((lane >> 3) & 1) * 8;   // ldmatrix row within tile
        int cxA = lane >> 2;                            // c-frag row
        uint32_t baseB = W1Hu + (uint32_t)((((lane >> 3) & 3) * 8 + (lane & 7)) * 16);

#pragma unroll
        for (int grp = 0; grp < 2; grp++) {
            int cy = 2 * w + grp;                       // pooled row
            float ac[4][4][4];
#pragma unroll
            for (int d = 0; d < 4; d++)
#pragma unroll
                for (int nt = 0; nt < 4; nt++)
#pragma unroll
                    for (int j = 0; j < 4; j++) ac[d][nt][j] = 0.f;

            uint32_t baseA[2];
#pragma unroll
            for (int pp = 0; pp < 2; pp++) {
                int d = 2 * pp + (lane >> 4);
                baseA[pp] = XHu + (uint32_t)((((2 * cy + (d >> 1)) * 34) + 2 * rr + (d & 1)) * 16);
            }

#pragma unroll
            for (int tap = 0; tap < 9; tap++) {
                uint32_t off = (uint32_t)((((tap / 3) * 34) + (tap % 3)) * 16);
                uint32_t a0[4], a1[4], bf[4];
                ldm4(a0, baseA[0] + off);               // d-tiles 0,1
                ldm4(a1, baseA[1] + off);               // d-tiles 2,3
                ldm4(bf, baseB + (uint32_t)(tap * 512));
#pragma unroll
                for (int nt = 0; nt < 4; nt++) {
                    mma1688(ac[0][nt], a0[0], a0[1], bf[nt]);
                    mma1688(ac[1][nt], a0[2], a0[3], bf[nt]);
                    mma1688(ac[2][nt], a1[0], a1[1], bf[nt]);
                    mma1688(ac[3][nt], a1[2], a1[3], bf[nt]);
                }
            }

            // epilogue: pool over d in-register, BN+ReLU, store fp16 A rows
            int s0 = (cy + 1) * 18 + (cxA + 1);
            int s1 = s0 + 8;
#pragma unroll
            for (int nt = 0; nt < 4; nt++) {
                float m00 = 0.f, m01 = 0.f, m10 = 0.f, m11 = 0.f;
#pragma unroll
                for (int d = 0; d < 4; d++) {
                    m00 = fmaxf(m00, fmaxf(0.f, ac[d][nt][0] * s1v[nt][0] + q1v[nt][0]));
                    m01 = fmaxf(m01, fmaxf(0.f, ac[d][nt][1] * s1v[nt][1] + q1v[nt][1]));
                    m10 = fmaxf(m10, fmaxf(0.f, ac[d][nt][2] * s1v[nt][0] + q1v[nt][0]));
                    m11 = fmaxf(m11, fmaxf(0.f, ac[d][nt][3] * s1v[nt][1] + q1v[nt][1]));
                }
                int oc0 = nt * 8 + 2 * (lane & 3);
                sts32(Au + (uint32_t)(s0 * A_STRIDE + 2 * oc0), h2pack(m00, m01));
                sts32(Au + (uint32_t)(s1 * A_STRIDE + 2 * oc0), h2pack(m10, m11));
            }
        }
    }
    __syncthreads();

    // ---- phase 3: conv2 via fp16 mma (9 taps, m16n8k16), barrier-free ----
    int xl   = lane & 15;
    int colh = lane >> 4;
    uint32_t b_lane = (uint32_t)((((lane >> 4) * 8 + (lane & 7)) * A_STRIDE) + ((lane >> 3) & 1) * 16);

    float acc[2][8][4];
#pragma unroll
    for (int mt = 0; mt < 2; mt++)
#pragma unroll
        for (int nt = 0; nt < 8; nt++)
#pragma unroll
            for (int j = 0; j < 4; j++) acc[mt][nt][j] = 0.f;

#pragma unroll 1
    for (int tap = 0; tap < 9; tap++) {
        uint32_t Bc = B2u + (uint32_t)(tap * 5120);
        int ky = tap / 3, kx = tap % 3;
        uint32_t arow0 = Au + (uint32_t)((((2 * w + ky) * 18) + xl + kx) * A_STRIDE + colh * 16);
        uint32_t arow1 = arow0 + 18 * A_STRIDE;

#pragma unroll
        for (int kc = 0; kc < 2; kc++) {
            uint32_t ko = kc * 32;
            uint32_t a0[4], a1[4];
            ldm4(a0, arow0 + ko);
            ldm4(a1, arow1 + ko);

            uint32_t bf[8][2];
#pragma unroll
            for (int g = 0; g < 4; g++) {
                uint32_t r[4];
                ldm4(r, Bc + b_lane + (uint32_t)(g * 16 * A_STRIDE) + ko);
                bf[g * 2][0] = r[0]; bf[g * 2][1] = r[1];
                bf[g * 2 + 1][0] = r[2]; bf[g * 2 + 1][1] = r[3];
            }
#pragma unroll
            for (int nt = 0; nt < 8; nt++) {
                mma16816(acc[0][nt], a0, bf[nt]);
                mma16816(acc[1][nt], a1, bf[nt]);
            }
        }
    }
    __syncthreads();

    // ---- phase 4: BN + ReLU + 2x2 pool (warp-local) -> h2s smem ----
    {
        int c0b  = 2 * (lane & 3);
        bool act = ((lane >> 2) & 1) == 0;
        int pos0 = w * 8 + (lane >> 3);       // pooled flat pos (py=w, px=lane>>3)
        int pos1 = pos0 + 4;
#pragma unroll
        for (int nt = 0; nt < 8; nt++) {
            int c0 = nt * 8 + c0b, c1 = c0 + 1;
            float s0 = sS2[c0], s1 = sS2[c1], q0 = sQ2[c0], q1 = sQ2[c1];
            float v0 = fmaxf(fmaxf(0.f, acc[0][nt][0] * s0 + q0), fmaxf(0.f, acc[1][nt][0] * s0 + q0));
            float v1 = fmaxf(fmaxf(0.f, acc[0][nt][1] * s1 + q1), fmaxf(0.f, acc[1][nt][1] * s1 + q1));
            float v2 = fmaxf(fmaxf(0.f, acc[0][nt][2] * s0 + q0), fmaxf(0.f, acc[1][nt][2] * s0 + q0));
            float v3 = fmaxf(fmaxf(0.f, acc[0][nt][3] * s1 + q1), fmaxf(0.f, acc[1][nt][3] * s1 + q1));
            v0 = fmaxf(v0, __shfl_xor_sync(0xffffffffu, v0, 4));
            v1 = fmaxf(v1, __shfl_xor_sync(0xffffffffu, v1, 4));
            v2 = fmaxf(v2, __shfl_xor_sync(0xffffffffu, v2, 4));
            v3 = fmaxf(v3, __shfl_xor_sync(0xffffffffu, v3, 4));
            if (act) {
                h2s[c0 * 64 + pos0] = v0;
                h2s[c1 * 64 + pos0] = v1;
                h2s[c0 * 64 + pos1] = v2;
                h2s[c1 * 64 + pos1] = v3;
            }
        }
    }
    __syncthreads();

    // ---- phase 5: coalesced fc GEMV (fe read as contiguous float4 stripes) ----
    const float4* fe4  = (const float4*)(fcw + (size_t)e * 40960);
    const float4* h2s4 = (const float4*)h2s;
    float fca[10];
#pragma unroll
    for (int o = 0; o < 10; o++) fca[o] = 0.f;
#pragma unroll
    for (int it = 0; it < 4; it++) {
        int j4 = it * 256 + tid;
        float4 h = h2s4[j4];
#pragma unroll
        for (int o = 0; o < 10; o++) {
            float4 wv = fe4[o * 1024 + j4];
            fca[o] += h.x * wv.x + h.y * wv.y + h.z * wv.z + h.w * wv.w;
        }
    }

    // ---- phase 6: reduce fc partials, write pair output ----
#pragma unroll
    for (int o = 0; o < 10; o++)
#pragma unroll
        for (int off = 16; off; off >>= 1)
            fca[o] += __shfl_xor_sync(0xffffffffu, fca[o], off);

    if (lane == 0)
#pragma unroll
        for (int o = 0; o < 10; o++) redm[w * 10 + o] = fca[o];
    __syncthreads();
    if (tid < 10) {
        float s = 0.f;
#pragma unroll
        for (int ww = 0; ww < 8; ww++) s += redm[ww * 10 + tid];
        g_pout[p * 10 + tid] = s + fcb[e * 10 + tid];
    }
}

// ---------------- combine: y = log(g0*exp(o0) + g1*exp(o1)) ----------------
__global__ void combine_kernel(float* __restrict__ out) {
    int idx = blockIdx.x * blockDim.x + threadIdx.x;
    if (idx >= BATCH * 10) return;
    int b = idx / 10, o = idx - b * 10;
    float g0 = g_gatev[2 * b], g1 = g_gatev[2 * b + 1];
    float c = g0 * expf(g_pout[(2 * b) * 10 + o]) + g1 * expf(g_pout[(2 * b + 1) * 10 + o]);
    if (c == 0.f) c = 2.2204460492503131e-16f;   // np.finfo(float).eps
    out[idx] = logf(c);
}

// ---------------- loss: CV^2(importance) + CV^2(load), deterministic ----------------
__global__ void loss_kernel(float* __restrict__ out, int out_size) {
    __shared__ float rimp[8 * 8];
    __shared__ float rcnt[8 * 8];
    int t = threadIdx.x;   // 256
    float imp[8], cnt[8];
#pragma unroll
    for (int i = 0; i < 8; i++) { imp[i] = 0.f; cnt[i] = 0.f; }
    for (int p = t; p < 2 * BATCH; p += 256) {
        int e = g_expid[p];
        imp[e] += g_gatev[p];
        cnt[e] += 1.f;
    }
#pragma unroll
    for (int off = 16; off; off >>= 1)
#pragma unroll
        for (int i = 0; i < 8; i++) {
            imp[i] += __shfl_xor_sync(0xffffffffu, imp[i], off);
            cnt[i] += __shfl_xor_sync(0xffffffffu, cnt[i], off);
        }
    if ((t & 31) == 0)
#pragma unroll
        for (int i = 0; i < 8; i++) {
            rimp[(t >> 5) * 8 + i] = imp[i];
            rcnt[(t >> 5) * 8 + i] = cnt[i];
        }
    __syncthreads();
    if (t == 0) {
        double si = 0, sl = 0, si2 = 0, sl2 = 0;
        for (int e = 0; e < 8; e++) {
            double vi = 0, vl = 0;
            for (int w = 0; w < 8; w++) { vi += rimp[w * 8 + e]; vl += rcnt[w * 8 + e]; }
            si += vi; sl += vl; si2 += vi * vi; sl2 += vl * vl;
        }
        double mi = si / 8.0, ml = sl / 8.0;
        double vari = (si2 - 8.0 * mi * mi) / 7.0;   // ddof=1
        double varl = (sl2 - 8.0 * ml * ml) / 7.0;
        double loss = (vari / (mi * mi + 1e-10) + varl / (ml * ml + 1e-10)) * 0.01;
        out[out_size - 1] = (float)loss;
    }
}

// ---------------- launch ----------------
extern "C" void kernel_launch(void* const* d_in, const int* in_sizes, int n_in,
                              void* d_out, int out_size) {
    const float* x   = (const float*)d_in[0];
    // d_in[1] = index (unused by reference math)
    const float* wg  = (const float*)d_in[2];
    const float* w1  = (const float*)d_in[3];
    const float* b1  = (const float*)d_in[4];
    const float* g1  = (const float*)d_in[5];
    const float* be1 = (const float*)d_in[6];
    const float* rm1 = (const float*)d_in[7];
    const float* rv1 = (const float*)d_in[8];
    const float* w2  = (const float*)d_in[9];
    const float* b2  = (const float*)d_in[10];
    const float* g2  = (const float*)d_in[11];
    const float* be2 = (const float*)d_in[12];
    const float* rm2 = (const float*)d_in[13];
    const float* rv2 = (const float*)d_in[14];
    const float* fcw = (const float*)d_in[15];
    const float* fcb = (const float*)d_in[16];
    float* out = (float*)d_out;

    cudaFuncSetAttribute(pair_kernel, cudaFuncAttributeMaxDynamicSharedMemorySize, SMEM_BYTES);

    eff_kernel<<<1, 512>>>(b1, g1, be1, rm1, rv1, b2, g2, be2, rm2, rv2);
    w2h_kernel<<<576, 256>>>(w2);
    w1h_kernel<<<27, 256>>>(w1);
    gate_kernel<<<BATCH, 128>>>(x, wg);
    pair_kernel<<<2 * BATCH, 256, SMEM_BYTES>>>(x, fcw, fcb);
    combine_kernel<<<(BATCH * 10 + 255) / 256, 256>>>(out);
    loss_kernel<<<1, 256>>>(out, out_size);
}

// round 10
// speedup vs baseline: 4.5777x; 1.0339x over previous
#include <cuda_runtime.h>
#include <cuda_fp16.h>
#include <cstdint>

#define NEXP  8
#define BATCH 4096
#define GS    8

// ---------------- device scratch (no allocations allowed) ----------------
__device__ float g_gs1[NEXP * 32];
__device__ float g_gb1[NEXP * 32];
__device__ float g_gs2[NEXP * 64];
__device__ float g_gb2[NEXP * 64];
__device__ int   g_expid[2 * BATCH];
__device__ float g_gatev[2 * BATCH];
__device__ float g_pout[2 * BATCH * 10];
// W2 in fp16, tap-major: [e][tap][oc64][ic0..31]
__device__ __half g_w2h[NEXP * 9 * 64 * 32];
// W1 in fp16, tap-major: [e][tap][oc32][k8: ic0..2, 0,0,0,0,0]  (zero-padded; .bss is zero-init)
__device__ __half g_w1h[NEXP * 9 * 32 * 8];

// ---------------- smem / mma helpers ----------------
static __device__ __forceinline__ uint32_t smem_u32(const void* p) {
    uint32_t a;
    asm("{ .reg .u64 t; cvta.to.shared.u64 t, %1; cvt.u32.u64 %0, t; }" : "=r"(a) : "l"(p));
    return a;
}
static __device__ __forceinline__ void sts32(uint32_t a, uint32_t v) {
    asm volatile("st.shared.b32 [%0], %1;" :: "r"(a), "r"(v) : "memory");
}
static __device__ __forceinline__ void sts128(uint32_t a, uint4 v) {
    asm volatile("st.shared.v4.b32 [%0], {%1,%2,%3,%4};" :: "r"(a), "r"(v.x), "r"(v.y), "r"(v.z), "r"(v.w) : "memory");
}
static __device__ __forceinline__ void ldm4(uint32_t* r, uint32_t addr) {
    asm volatile("ldmatrix.sync.aligned.m8n8.x4.shared.b16 {%0,%1,%2,%3}, [%4];"
                 : "=r"(r[0]), "=r"(r[1]), "=r"(r[2]), "=r"(r[3]) : "r"(addr));
}
static __device__ __forceinline__ void mma16816(float* d, const uint32_t* a, const uint32_t* b) {
    asm volatile("mma.sync.aligned.m16n8k16.row.col.f32.f16.f16.f32 "
                 "{%0,%1,%2,%3}, {%4,%5,%6,%7}, {%8,%9}, {%0,%1,%2,%3};"
                 : "+f"(d[0]), "+f"(d[1]), "+f"(d[2]), "+f"(d[3])
                 : "r"(a[0]), "r"(a[1]), "r"(a[2]), "r"(a[3]), "r"(b[0]), "r"(b[1]));
}
static __device__ __forceinline__ void mma1688(float* d, uint32_t a0, uint32_t a1, uint32_t b0) {
    asm volatile("mma.sync.aligned.m16n8k8.row.col.f32.f16.f16.f32 "
                 "{%0,%1,%2,%3}, {%4,%5}, {%6}, {%0,%1,%2,%3};"
                 : "+f"(d[0]), "+f"(d[1]), "+f"(d[2]), "+f"(d[3])
                 : "r"(a0), "r"(a1), "r"(b0));
}
static __device__ __forceinline__ uint32_t h2pack(float a, float b) {
    return ((uint32_t)__half_as_ushort(__float2half_rn(b)) << 16)
         | (uint32_t)__half_as_ushort(__float2half_rn(a));
}

// ---------------- fold BN (eval mode) into scale/shift ----------------
__global__ void eff_kernel(const float* __restrict__ b1, const float* __restrict__ g1,
                           const float* __restrict__ be1, const float* __restrict__ rm1,
                           const float* __restrict__ rv1,
                           const float* __restrict__ b2, const float* __restrict__ g2,
                           const float* __restrict__ be2, const float* __restrict__ rm2,
                           const float* __restrict__ rv2) {
    int t = threadIdx.x;
    if (t < NEXP * 32) {
        float s = g1[t] / sqrtf(rv1[t] + 1e-5f);
        g_gs1[t] = s;
        g_gb1[t] = (b1[t] - rm1[t]) * s + be1[t];
    }
    if (t < NEXP * 64) {
        float s = g2[t] / sqrtf(rv2[t] + 1e-5f);
        g_gs2[t] = s;
        g_gb2[t] = (b2[t] - rm2[t]) * s + be2[t];
    }
}

// ---------------- prep: W2 -> fp16, tap-major ----------------
__global__ void w2h_kernel(const float* __restrict__ w2) {
    int idx = blockIdx.x * 256 + threadIdx.x;      // 147456 total
    if (idx >= NEXP * 9 * 64 * 32) return;
    int ic  = idx & 31;
    int oc  = (idx >> 5) & 63;
    int r   = idx >> 11;
    int tap = r % 9;
    int e   = r / 9;
    float w = w2[(((size_t)e * 64 + oc) * 32 + ic) * 9 + tap];
    g_w2h[((size_t)(e * 9 + tap) * 64 + oc) * 32 + ic] = __float2half_rn(w);
}

// ---------------- prep: W1 -> fp16, tap-major, k8-padded ----------------
__global__ void w1h_kernel(const float* __restrict__ w1) {
    int idx = blockIdx.x * 256 + threadIdx.x;      // 6912 total
    if (idx >= NEXP * 9 * 32 * 3) return;
    int ic  = idx % 3;
    int t   = idx / 3;
    int oc  = t % 32;  t /= 32;
    int tap = t % 9;
    int e   = t / 9;
    float v = w1[(((size_t)e * 32 + oc) * 3 + ic) * 9 + tap];
    g_w1h[((size_t)(e * 9 + tap) * 32 + oc) * 8 + ic] = __float2half_rn(v);
}

// ---------------- gating: 8 samples per block, float4 both sides ----------------
__global__ void __launch_bounds__(256) gate_kernel(const float* __restrict__ x,
                                                   const float* __restrict__ wg) {
    __shared__ float red[8][64];
    int b0 = blockIdx.x * GS;
    int t  = threadIdx.x;            // 256 threads
    int lane = t & 31, w = t >> 5;
    const float4* xb4 = (const float4*)(x + (size_t)b0 * 3072);

    float p[GS][8];
#pragma unroll
    for (int s = 0; s < GS; s++)
#pragma unroll
        for (int i = 0; i < 8; i++) p[s][i] = 0.f;

#pragma unroll
    for (int it = 0; it < 3; it++) {
        int j4 = t + it * 256;       // float4 index 0..767
        const float4* w4 = (const float4*)(wg + (size_t)j4 * 32);
        float4 xv[GS];
#pragma unroll
        for (int s = 0; s < GS; s++) xv[s] = xb4[s * 768 + j4];
#pragma unroll
        for (int k = 0; k < 4; k++) {
            float4 w0 = w4[2 * k], w1 = w4[2 * k + 1];
#pragma unroll
            for (int s = 0; s < GS; s++) {
                float xk = (k == 0) ? xv[s].x : (k == 1) ? xv[s].y : (k == 2) ? xv[s].z : xv[s].w;
                p[s][0] += xk * w0.x; p[s][1] += xk * w0.y; p[s][2] += xk * w0.z; p[s][3] += xk * w0.w;
                p[s][4] += xk * w1.x; p[s][5] += xk * w1.y; p[s][6] += xk * w1.z; p[s][7] += xk * w1.w;
            }
        }
    }
#pragma unroll
    for (int off = 16; off; off >>= 1)
#pragma unroll
        for (int s = 0; s < GS; s++)
#pragma unroll
            for (int i = 0; i < 8; i++) p[s][i] += __shfl_xor_sync(0xffffffffu, p[s][i], off);
    if (lane == 0)
#pragma unroll
        for (int s = 0; s < GS; s++)
#pragma unroll
            for (int i = 0; i < 8; i++) red[w][s * 8 + i] = p[s][i];
    __syncthreads();
    if (t < 64) {
        float sum = 0.f;
#pragma unroll
        for (int ww = 0; ww < 8; ww++) sum += red[ww][t];
        red[0][t] = sum;
    }
    __syncthreads();
    if (t < GS) {
        float lg[8];
#pragma unroll
        for (int i = 0; i < 8; i++) lg[i] = red[0][t * 8 + i];
        // top-2, first-occurrence tie order (matches jax.lax.top_k)
        int i0 = 0;
#pragma unroll
        for (int e = 1; e < 8; e++) if (lg[e] > lg[i0]) i0 = e;
        int i1 = -1;
#pragma unroll
        for (int e = 0; e < 8; e++) {
            if (e == i0) continue;
            if (i1 < 0 || lg[e] > lg[i1]) i1 = e;
        }
        float t1  = expf(lg[i1] - lg[i0]);     // <= 1
        float inv = 1.f / (1.f + t1);
        int b = b0 + t;
        g_expid[2 * b]     = i0;
        g_gatev[2 * b]     = inv;
        g_expid[2 * b + 1] = i1;
        g_gatev[2 * b + 1] = t1 * inv;
    }
}

// ---------------- fused expert kernel: fp16 mma for BOTH convs ----------------
// smem layout (bytes):
//  A    [0, 25920):       324 rows x 80B (conv2 A: [s][32 oc fp16] + 16B pad)
//                         reused after phase 3 as h2s[4096] f32 (16KB)
//  B2   [25920, 72000):   9 taps x 64 rows x 80B (conv2 weights, all-resident)
//  XH   [72000, 90496):   conv1 input fp16, 34x34 grid x 16B rows [ic0..2, 0pad]
//  W1H  [90496, 95104):   9 taps x 32 rows x 16B (conv1 weights)
//  sS1  [95104,+128) sQ1 [95232,+128) sS2 [95360,+256) sQ2 [95616,+256) red [95872,+320)
#define A_STRIDE 80
#define B2_OFF   25920
#define XH_OFF   72000
#define W1H_OFF  90496
#define SS1_OFF  95104
#define SQ1_OFF  95232
#define SS2_OFF  95360
#define SQ2_OFF  95616
#define RED_OFF  95872
#define SMEM_BYTES (RED_OFF + 320)

__global__ void __launch_bounds__(256, 2) pair_kernel(
    const float* __restrict__ x,
    const float* __restrict__ fcw, const float* __restrict__ fcb) {
    extern __shared__ __align__(128) char sb[];
    uint32_t Au   = smem_u32(sb);
    uint32_t B2u  = Au + B2_OFF;
    uint32_t XHu  = Au + XH_OFF;
    uint32_t W1Hu = Au + W1H_OFF;
    float* sS1  = (float*)(sb + SS1_OFF);
    float* sQ1  = (float*)(sb + SQ1_OFF);
    float* sS2  = (float*)(sb + SS2_OFF);
    float* sQ2  = (float*)(sb + SQ2_OFF);
    float* redm = (float*)(sb + RED_OFF);
    float* h2s  = (float*)sb;                     // overlays A after phase 3

    int p    = blockIdx.x;
    int b    = p >> 1;
    int e    = g_expid[p];
    int tid  = threadIdx.x;
    int lane = tid & 31;
    int w    = tid >> 5;

    // ---- phase 0: zero A halo + XH; load BN consts ----
    for (int i = tid; i < 1620; i += 256) sts128(Au + i * 16, make_uint4(0, 0, 0, 0));
    for (int i = tid; i < 1156; i += 256) sts128(XHu + i * 16, make_uint4(0, 0, 0, 0));
    if (tid < 32) {
        sS1[tid] = g_gs1[e * 32 + tid];
        sQ1[tid] = g_gb1[e * 32 + tid];
    }
    if (tid < 64) {
        sS2[tid] = g_gs2[e * 64 + tid];
        sQ2[tid] = g_gb2[e * 64 + tid];
    }
    __syncthreads();

    // ---- phase 1: stage XH interior (x->fp16), W1H, and all 9 B2 tap tiles ----
    {
        const float* xb = x + (size_t)b * 3072;
#pragma unroll
        for (int it = 0; it < 4; it++) {
            int pp = tid + it * 256;              // position 0..1023
            float v0 = xb[pp];
            float v1 = xb[1024 + pp];
            float v2 = xb[2048 + pp];
            uint4 u;
            u.x = h2pack(v0, v1);
            u.y = (uint32_t)__half_as_ushort(__float2half_rn(v2));
            u.z = 0; u.w = 0;
            int y = pp >> 5, xx = pp & 31;
            sts128(XHu + (uint32_t)(((y + 1) * 34 + xx + 1) * 16), u);
        }
        const uint4* w1src = (const uint4*)(g_w1h) + (size_t)e * 9 * 32;   // 288 uint4
        for (int i = tid; i < 288; i += 256)
            sts128(W1Hu + (uint32_t)(i * 16), w1src[i]);
        const uint4* w2src = (const uint4*)(g_w2h) + (size_t)e * 9 * 256;  // 2304 uint4
#pragma unroll
        for (int j = 0; j < 9; j++) {
            int i = tid + j * 256;
            sts128(B2u + (uint32_t)((i >> 2) * A_STRIDE + (i & 3) * 16), w2src[i]);
        }
    }
    __syncthreads();

    // ---- phase 2: conv1 via fp16 mma (9 taps, m16n8k8), BN+ReLU+pool -> A rows ----
    {
        float s1v[4][2], q1v[4][2];
#pragma unroll
        for (int nt = 0; nt < 4; nt++) {
            int oc0 = nt * 8 + 2 * (lane & 3);
            s1v[nt][0] = sS1[oc0];     s1v[nt][1] = sS1[oc0 + 1];
            q1v[nt][0] = sQ1[oc0];     q1v[nt][1] = sQ1[oc0 + 1];
        }
        int rr  = (lane & 7) + ((lane >> 3) & 1) * 8;   // ldmatrix row within tile
        int cxA = lane >> 2;                            // c-frag row
        uint32_t baseB = W1Hu + (uint32_t)((((lane >> 3) & 3) * 8 + (lane & 7)) * 16);

#pragma unroll
        for (int grp = 0; grp < 2; grp++) {
            int cy = 2 * w + grp;                       // pooled row
            float ac[4][4][4];
#pragma unroll
            for (int d = 0; d < 4; d++)
#pragma unroll
                for (int nt = 0; nt < 4; nt++)
#pragma unroll
                    for (int j = 0; j < 4; j++) ac[d][nt][j] = 0.f;

            uint32_t baseA[2];
#pragma unroll
            for (int pp = 0; pp < 2; pp++) {
                int d = 2 * pp + (lane >> 4);
                baseA[pp] = XHu + (uint32_t)((((2 * cy + (d >> 1)) * 34) + 2 * rr + (d & 1)) * 16);
            }

#pragma unroll
            for (int tap = 0; tap < 9; tap++) {
                uint32_t off = (uint32_t)((((tap / 3) * 34) + (tap % 3)) * 16);
                uint32_t a0[4], a1[4], bf[4];
                ldm4(a0, baseA[0] + off);               // d-tiles 0,1
                ldm4(a1, baseA[1] + off);               // d-tiles 2,3
                ldm4(bf, baseB + (uint32_t)(tap * 512));
#pragma unroll
                for (int nt = 0; nt < 4; nt++) {
                    mma1688(ac[0][nt], a0[0], a0[1], bf[nt]);
                    mma1688(ac[1][nt], a0[2], a0[3], bf[nt]);
                    mma1688(ac[2][nt], a1[0], a1[1], bf[nt]);
                    mma1688(ac[3][nt], a1[2], a1[3], bf[nt]);
                }
            }

            // epilogue: pool over d in-register, BN+ReLU, store fp16 A rows
            int s0 = (cy + 1) * 18 + (cxA + 1);
            int s1 = s0 + 8;
#pragma unroll
            for (int nt = 0; nt < 4; nt++) {
                float m00 = 0.f, m01 = 0.f, m10 = 0.f, m11 = 0.f;
#pragma unroll
                for (int d = 0; d < 4; d++) {
                    m00 = fmaxf(m00, fmaxf(0.f, ac[d][nt][0] * s1v[nt][0] + q1v[nt][0]));
                    m01 = fmaxf(m01, fmaxf(0.f, ac[d][nt][1] * s1v[nt][1] + q1v[nt][1]));
                    m10 = fmaxf(m10, fmaxf(0.f, ac[d][nt][2] * s1v[nt][0] + q1v[nt][0]));
                    m11 = fmaxf(m11, fmaxf(0.f, ac[d][nt][3] * s1v[nt][1] + q1v[nt][1]));
                }
                int oc0 = nt * 8 + 2 * (lane & 3);
                sts32(Au + (uint32_t)(s0 * A_STRIDE + 2 * oc0), h2pack(m00, m01));
                sts32(Au + (uint32_t)(s1 * A_STRIDE + 2 * oc0), h2pack(m10, m11));
            }
        }
    }
    __syncthreads();

    // ---- phase 3: conv2 via fp16 mma (9 taps, m16n8k16), unroll for ILP ----
    int xl   = lane & 15;
    int colh = lane >> 4;
    uint32_t b_lane = (uint32_t)((((lane >> 4) * 8 + (lane & 7)) * A_STRIDE) + ((lane >> 3) & 1) * 16);

    float acc[2][8][4];
#pragma unroll
    for (int mt = 0; mt < 2; mt++)
#pragma unroll
        for (int nt = 0; nt < 8; nt++)
#pragma unroll
            for (int j = 0; j < 4; j++) acc[mt][nt][j] = 0.f;

#pragma unroll 3
    for (int tap = 0; tap < 9; tap++) {
        uint32_t Bc = B2u + (uint32_t)(tap * 5120);
        int ky = tap / 3, kx = tap % 3;
        uint32_t arow0 = Au + (uint32_t)((((2 * w + ky) * 18) + xl + kx) * A_STRIDE + colh * 16);
        uint32_t arow1 = arow0 + 18 * A_STRIDE;

#pragma unroll
        for (int kc = 0; kc < 2; kc++) {
            uint32_t ko = kc * 32;
            uint32_t a0[4], a1[4];
            ldm4(a0, arow0 + ko);
            ldm4(a1, arow1 + ko);

            uint32_t bf[8][2];
#pragma unroll
            for (int g = 0; g < 4; g++) {
                uint32_t r[4];
                ldm4(r, Bc + b_lane + (uint32_t)(g * 16 * A_STRIDE) + ko);
                bf[g * 2][0] = r[0]; bf[g * 2][1] = r[1];
                bf[g * 2 + 1][0] = r[2]; bf[g * 2 + 1][1] = r[3];
            }
#pragma unroll
            for (int nt = 0; nt < 8; nt++) {
                mma16816(acc[0][nt], a0, bf[nt]);
                mma16816(acc[1][nt], a1, bf[nt]);
            }
        }
    }
    __syncthreads();

    // ---- phase 4: BN + ReLU + 2x2 pool (warp-local) -> h2s smem ----
    {
        int c0b  = 2 * (lane & 3);
        bool act = ((lane >> 2) & 1) == 0;
        int pos0 = w * 8 + (lane >> 3);       // pooled flat pos (py=w, px=lane>>3)
        int pos1 = pos0 + 4;
#pragma unroll
        for (int nt = 0; nt < 8; nt++) {
            int c0 = nt * 8 + c0b, c1 = c0 + 1;
            float s0 = sS2[c0], s1 = sS2[c1], q0 = sQ2[c0], q1 = sQ2[c1];
            float v0 = fmaxf(fmaxf(0.f, acc[0][nt][0] * s0 + q0), fmaxf(0.f, acc[1][nt][0] * s0 + q0));
            float v1 = fmaxf(fmaxf(0.f, acc[0][nt][1] * s1 + q1), fmaxf(0.f, acc[1][nt][1] * s1 + q1));
            float v2 = fmaxf(fmaxf(0.f, acc[0][nt][2] * s0 + q0), fmaxf(0.f, acc[1][nt][2] * s0 + q0));
            float v3 = fmaxf(fmaxf(0.f, acc[0][nt][3] * s1 + q1), fmaxf(0.f, acc[1][nt][3] * s1 + q1));
            v0 = fmaxf(v0, __shfl_xor_sync(0xffffffffu, v0, 4));
            v1 = fmaxf(v1, __shfl_xor_sync(0xffffffffu, v1, 4));
            v2 = fmaxf(v2, __shfl_xor_sync(0xffffffffu, v2, 4));
            v3 = fmaxf(v3, __shfl_xor_sync(0xffffffffu, v3, 4));
            if (act) {
                h2s[c0 * 64 + pos0] = v0;
                h2s[c1 * 64 + pos0] = v1;
                h2s[c0 * 64 + pos1] = v2;
                h2s[c1 * 64 + pos1] = v3;
            }
        }
    }
    __syncthreads();

    // ---- phase 5: coalesced fc GEMV (fe read as contiguous float4 stripes) ----
    const float4* fe4  = (const float4*)(fcw + (size_t)e * 40960);
    const float4* h2s4 = (const float4*)h2s;
    float fca[10];
#pragma unroll
    for (int o = 0; o < 10; o++) fca[o] = 0.f;
#pragma unroll
    for (int it = 0; it < 4; it++) {
        int j4 = it * 256 + tid;
        float4 h = h2s4[j4];
#pragma unroll
        for (int o = 0; o < 10; o++) {
            float4 wv = fe4[o * 1024 + j4];
            fca[o] += h.x * wv.x + h.y * wv.y + h.z * wv.z + h.w * wv.w;
        }
    }

    // ---- phase 6: reduce fc partials, write pair output ----
#pragma unroll
    for (int o = 0; o < 10; o++)
#pragma unroll
        for (int off = 16; off; off >>= 1)
            fca[o] += __shfl_xor_sync(0xffffffffu, fca[o], off);

    if (lane == 0)
#pragma unroll
        for (int o = 0; o < 10; o++) redm[w * 10 + o] = fca[o];
    __syncthreads();
    if (tid < 10) {
        float s = 0.f;
#pragma unroll
        for (int ww = 0; ww < 8; ww++) s += redm[ww * 10 + tid];
        g_pout[p * 10 + tid] = s + fcb[e * 10 + tid];
    }
}

// ---------------- combine: y = log(g0*exp(o0) + g1*exp(o1)) ----------------
__global__ void combine_kernel(float* __restrict__ out) {
    int idx = blockIdx.x * blockDim.x + threadIdx.x;
    if (idx >= BATCH * 10) return;
    int b = idx / 10, o = idx - b * 10;
    float g0 = g_gatev[2 * b], g1 = g_gatev[2 * b + 1];
    float c = g0 * expf(g_pout[(2 * b) * 10 + o]) + g1 * expf(g_pout[(2 * b + 1) * 10 + o]);
    if (c == 0.f) c = 2.2204460492503131e-16f;   // np.finfo(float).eps
    out[idx] = logf(c);
}

// ---------------- loss: CV^2(importance) + CV^2(load), deterministic ----------------
__global__ void loss_kernel(float* __restrict__ out, int out_size) {
    __shared__ float rimp[8 * 8];
    __shared__ float rcnt[8 * 8];
    int t = threadIdx.x;   // 256
    float imp[8], cnt[8];
#pragma unroll
    for (int i = 0; i < 8; i++) { imp[i] = 0.f; cnt[i] = 0.f; }
    for (int p = t; p < 2 * BATCH; p += 256) {
        int e = g_expid[p];
        imp[e] += g_gatev[p];
        cnt[e] += 1.f;
    }
#pragma unroll
    for (int off = 16; off; off >>= 1)
#pragma unroll
        for (int i = 0; i < 8; i++) {
            imp[i] += __shfl_xor_sync(0xffffffffu, imp[i], off);
            cnt[i] += __shfl_xor_sync(0xffffffffu, cnt[i], off);
        }
    if ((t & 31) == 0)
#pragma unroll
        for (int i = 0; i < 8; i++) {
            rimp[(t >> 5) * 8 + i] = imp[i];
            rcnt[(t >> 5) * 8 + i] = cnt[i];
        }
    __syncthreads();
    if (t == 0) {
        double si = 0, sl = 0, si2 = 0, sl2 = 0;
        for (int e = 0; e < 8; e++) {
            double vi = 0, vl = 0;
            for (int w = 0; w < 8; w++) { vi += rimp[w * 8 + e]; vl += rcnt[w * 8 + e]; }
            si += vi; sl += vl; si2 += vi * vi; sl2 += vl * vl;
        }
        double mi = si / 8.0, ml = sl / 8.0;
        double vari = (si2 - 8.0 * mi * mi) / 7.0;   // ddof=1
        double varl = (sl2 - 8.0 * ml * ml) / 7.0;
        double loss = (vari / (mi * mi + 1e-10) + varl / (ml * ml + 1e-10)) * 0.01;
        out[out_size - 1] = (float)loss;
    }
}

// ---------------- launch ----------------
extern "C" void kernel_launch(void* const* d_in, const int* in_sizes, int n_in,
                              void* d_out, int out_size) {
    const float* x   = (const float*)d_in[0];
    // d_in[1] = index (unused by reference math)
    const float* wg  = (const float*)d_in[2];
    const float* w1  = (const float*)d_in[3];
    const float* b1  = (const float*)d_in[4];
    const float* g1  = (const float*)d_in[5];
    const float* be1 = (const float*)d_in[6];
    const float* rm1 = (const float*)d_in[7];
    const float* rv1 = (const float*)d_in[8];
    const float* w2  = (const float*)d_in[9];
    const float* b2  = (const float*)d_in[10];
    const float* g2  = (const float*)d_in[11];
    const float* be2 = (const float*)d_in[12];
    const float* rm2 = (const float*)d_in[13];
    const float* rv2 = (const float*)d_in[14];
    const float* fcw = (const float*)d_in[15];
    const float* fcb = (const float*)d_in[16];
    float* out = (float*)d_out;

    cudaFuncSetAttribute(pair_kernel, cudaFuncAttributeMaxDynamicSharedMemorySize, SMEM_BYTES);

    eff_kernel<<<1, 512>>>(b1, g1, be1, rm1, rv1, b2, g2, be2, rm2, rv2);
    w2h_kernel<<<576, 256>>>(w2);
    w1h_kernel<<<27, 256>>>(w1);
    gate_kernel<<<BATCH / GS, 256>>>(x, wg);
    pair_kernel<<<2 * BATCH, 256, SMEM_BYTES>>>(x, fcw, fcb);
    combine_kernel<<<(BATCH * 10 + 255) / 256, 256>>>(out);
    loss_kernel<<<1, 256>>>(out, out_size);
}

// round 12
// speedup vs baseline: 4.6173x; 1.0086x over previous
#include <cuda_runtime.h>
#include <cuda_fp16.h>
#include <cstdint>

#define NEXP  8
#define BATCH 4096
#define GS    4

// ---------------- device scratch (no allocations allowed) ----------------
__device__ float g_gs1[NEXP * 32];
__device__ float g_gb1[NEXP * 32];
__device__ float g_gs2[NEXP * 64];
__device__ float g_gb2[NEXP * 64];
__device__ int   g_expid[2 * BATCH];
__device__ float g_gatev[2 * BATCH];
__device__ float g_pout[2 * BATCH * 10];
// W2 in fp16, tap-major: [e][tap][oc64][ic0..31]
__device__ __half g_w2h[NEXP * 9 * 64 * 32];
// W1 in fp16, tap-major: [e][tap][oc32][k8: ic0..2, 0...]  (zero-padded; .bss zero-init)
__device__ __half g_w1h[NEXP * 9 * 32 * 8];
// fc weights in fp16: [e][o10][j4096]
__device__ __half g_fcwh[NEXP * 10 * 4096];

// ---------------- smem / mma helpers ----------------
static __device__ __forceinline__ uint32_t smem_u32(const void* p) {
    uint32_t a;
    asm("{ .reg .u64 t; cvta.to.shared.u64 t, %1; cvt.u32.u64 %0, t; }" : "=r"(a) : "l"(p));
    return a;
}
static __device__ __forceinline__ void sts32(uint32_t a, uint32_t v) {
    asm volatile("st.shared.b32 [%0], %1;" :: "r"(a), "r"(v) : "memory");
}
static __device__ __forceinline__ void sts128(uint32_t a, uint4 v) {
    asm volatile("st.shared.v4.b32 [%0], {%1,%2,%3,%4};" :: "r"(a), "r"(v.x), "r"(v.y), "r"(v.z), "r"(v.w) : "memory");
}
static __device__ __forceinline__ void ldm4(uint32_t* r, uint32_t addr) {
    asm volatile("ldmatrix.sync.aligned.m8n8.x4.shared.b16 {%0,%1,%2,%3}, [%4];"
                 : "=r"(r[0]), "=r"(r[1]), "=r"(r[2]), "=r"(r[3]) : "r"(addr));
}
static __device__ __forceinline__ void mma16816(float* d, const uint32_t* a, const uint32_t* b) {
    asm volatile("mma.sync.aligned.m16n8k16.row.col.f32.f16.f16.f32 "
                 "{%0,%1,%2,%3}, {%4,%5,%6,%7}, {%8,%9}, {%0,%1,%2,%3};"
                 : "+f"(d[0]), "+f"(d[1]), "+f"(d[2]), "+f"(d[3])
                 : "r"(a[0]), "r"(a[1]), "r"(a[2]), "r"(a[3]), "r"(b[0]), "r"(b[1]));
}
static __device__ __forceinline__ void mma1688(float* d, uint32_t a0, uint32_t a1, uint32_t b0) {
    asm volatile("mma.sync.aligned.m16n8k8.row.col.f32.f16.f16.f32 "
                 "{%0,%1,%2,%3}, {%4,%5}, {%6}, {%0,%1,%2,%3};"
                 : "+f"(d[0]), "+f"(d[1]), "+f"(d[2]), "+f"(d[3])
                 : "r"(a0), "r"(a1), "r"(b0));
}
static __device__ __forceinline__ uint32_t h2pack(float a, float b) {
    return ((uint32_t)__half_as_ushort(__float2half_rn(b)) << 16)
         | (uint32_t)__half_as_ushort(__float2half_rn(a));
}

// ---------------- fold BN (eval mode) into scale/shift ----------------
__global__ void eff_kernel(const float* __restrict__ b1, const float* __restrict__ g1,
                           const float* __restrict__ be1, const float* __restrict__ rm1,
                           const float* __restrict__ rv1,
                           const float* __restrict__ b2, const float* __restrict__ g2,
                           const float* __restrict__ be2, const float* __restrict__ rm2,
                           const float* __restrict__ rv2) {
    int t = threadIdx.x;
    if (t < NEXP * 32) {
        float s = g1[t] / sqrtf(rv1[t] + 1e-5f);
        g_gs1[t] = s;
        g_gb1[t] = (b1[t] - rm1[t]) * s + be1[t];
    }
    if (t < NEXP * 64) {
        float s = g2[t] / sqrtf(rv2[t] + 1e-5f);
        g_gs2[t] = s;
        g_gb2[t] = (b2[t] - rm2[t]) * s + be2[t];
    }
}

// ---------------- prep: W2 -> fp16, tap-major ----------------
__global__ void w2h_kernel(const float* __restrict__ w2) {
    int idx = blockIdx.x * 256 + threadIdx.x;      // 147456 total
    if (idx >= NEXP * 9 * 64 * 32) return;
    int ic  = idx & 31;
    int oc  = (idx >> 5) & 63;
    int r   = idx >> 11;
    int tap = r % 9;
    int e   = r / 9;
    float w = w2[(((size_t)e * 64 + oc) * 32 + ic) * 9 + tap];
    g_w2h[((size_t)(e * 9 + tap) * 64 + oc) * 32 + ic] = __float2half_rn(w);
}

// ---------------- prep: W1 -> fp16, tap-major, k8-padded ----------------
__global__ void w1h_kernel(const float* __restrict__ w1) {
    int idx = blockIdx.x * 256 + threadIdx.x;      // 6912 total
    if (idx >= NEXP * 9 * 32 * 3) return;
    int ic  = idx % 3;
    int t   = idx / 3;
    int oc  = t % 32;  t /= 32;
    int tap = t % 9;
    int e   = t / 9;
    float v = w1[(((size_t)e * 32 + oc) * 3 + ic) * 9 + tap];
    g_w1h[((size_t)(e * 9 + tap) * 32 + oc) * 8 + ic] = __float2half_rn(v);
}

// ---------------- prep: fcw -> fp16 ----------------
__global__ void fcwh_kernel(const float* __restrict__ fcw) {
    int idx = blockIdx.x * 256 + threadIdx.x;      // 327680 total
    if (idx >= NEXP * 10 * 4096) return;
    g_fcwh[idx] = __float2half_rn(fcw[idx]);
}

// ---------------- gating: 4 samples per block, float4 both sides ----------------
__global__ void __launch_bounds__(256) gate_kernel(const float* __restrict__ x,
                                                   const float* __restrict__ wg) {
    __shared__ float red[8][GS * 8];
    int b0 = blockIdx.x * GS;
    int t  = threadIdx.x;            // 256 threads
    int lane = t & 31, w = t >> 5;
    const float4* xb4 = (const float4*)(x + (size_t)b0 * 3072);

    float p[GS][8];
#pragma unroll
    for (int s = 0; s < GS; s++)
#pragma unroll
        for (int i = 0; i < 8; i++) p[s][i] = 0.f;

#pragma unroll
    for (int it = 0; it < 3; it++) {
        int j4 = t + it * 256;       // float4 index 0..767
        const float4* w4 = (const float4*)(wg + (size_t)j4 * 32);
        float4 xv[GS];
#pragma unroll
        for (int s = 0; s < GS; s++) xv[s] = xb4[s * 768 + j4];
#pragma unroll
        for (int k = 0; k < 4; k++) {
            float4 w0 = w4[2 * k], w1 = w4[2 * k + 1];
#pragma unroll
            for (int s = 0; s < GS; s++) {
                float xk = (k == 0) ? xv[s].x : (k == 1) ? xv[s].y : (k == 2) ? xv[s].z : xv[s].w;
                p[s][0] += xk * w0.x; p[s][1] += xk * w0.y; p[s][2] += xk * w0.z; p[s][3] += xk * w0.w;
                p[s][4] += xk * w1.x; p[s][5] += xk * w1.y; p[s][6] += xk * w1.z; p[s][7] += xk * w1.w;
            }
        }
    }
#pragma unroll
    for (int off = 16; off; off >>= 1)
#pragma unroll
        for (int s = 0; s < GS; s++)
#pragma unroll
            for (int i = 0; i < 8; i++) p[s][i] += __shfl_xor_sync(0xffffffffu, p[s][i], off);
    if (lane == 0)
#pragma unroll
        for (int s = 0; s < GS; s++)
#pragma unroll
            for (int i = 0; i < 8; i++) red[w][s * 8 + i] = p[s][i];
    __syncthreads();
    if (t < GS * 8) {
        float sum = 0.f;
#pragma unroll
        for (int ww = 0; ww < 8; ww++) sum += red[ww][t];
        red[0][t] = sum;
    }
    __syncthreads();
    if (t < GS) {
        float lg[8];
#pragma unroll
        for (int i = 0; i < 8; i++) lg[i] = red[0][t * 8 + i];
        // top-2, first-occurrence tie order (matches jax.lax.top_k)
        int i0 = 0;
#pragma unroll
        for (int e = 1; e < 8; e++) if (lg[e] > lg[i0]) i0 = e;
        int i1 = -1;
#pragma unroll
        for (int e = 0; e < 8; e++) {
            if (e == i0) continue;
            if (i1 < 0 || lg[e] > lg[i1]) i1 = e;
        }
        float t1  = expf(lg[i1] - lg[i0]);     // <= 1
        float inv = 1.f / (1.f + t1);
        int b = b0 + t;
        g_expid[2 * b]     = i0;
        g_gatev[2 * b]     = inv;
        g_expid[2 * b + 1] = i1;
        g_gatev[2 * b + 1] = t1 * inv;
    }
}

// ---------------- fused expert kernel: fp16 mma for BOTH convs ----------------
// smem layout (bytes):
//  A    [0, 25920):       324 rows x 80B (conv2 A: [s][32 oc fp16] + 16B pad)
//                         reused after phase 3 as h2s[4096] f32 (16KB)
//  B2   [25920, 72000):   9 taps x 64 rows x 80B (conv2 weights, all-resident)
//  XH   [72000, 90496):   conv1 input fp16, 34x34 grid x 16B rows [ic0..2, 0pad]
//  W1H  [90496, 95104):   9 taps x 32 rows x 16B (conv1 weights)
//  sS1  [95104,+128) sQ1 [95232,+128) sS2 [95360,+256) sQ2 [95616,+256) red [95872,+320)
#define A_STRIDE 80
#define B2_OFF   25920
#define XH_OFF   72000
#define W1H_OFF  90496
#define SS1_OFF  95104
#define SQ1_OFF  95232
#define SS2_OFF  95360
#define SQ2_OFF  95616
#define RED_OFF  95872
#define SMEM_BYTES (RED_OFF + 320)

__global__ void __launch_bounds__(256, 2) pair_kernel(
    const float* __restrict__ x, const float* __restrict__ fcb) {
    extern __shared__ __align__(128) char sb[];
    uint32_t Au   = smem_u32(sb);
    uint32_t B2u  = Au + B2_OFF;
    uint32_t XHu  = Au + XH_OFF;
    uint32_t W1Hu = Au + W1H_OFF;
    float* sS1  = (float*)(sb + SS1_OFF);
    float* sQ1  = (float*)(sb + SQ1_OFF);
    float* sS2  = (float*)(sb + SS2_OFF);
    float* sQ2  = (float*)(sb + SQ2_OFF);
    float* redm = (float*)(sb + RED_OFF);
    float* h2s  = (float*)sb;                     // overlays A after phase 3

    int p    = blockIdx.x;
    int b    = p >> 1;
    int e    = g_expid[p];
    int tid  = threadIdx.x;
    int lane = tid & 31;
    int w    = tid >> 5;

    // ---- phase 0: zero A halo + XH; load BN consts ----
    for (int i = tid; i < 1620; i += 256) sts128(Au + i * 16, make_uint4(0, 0, 0, 0));
    for (int i = tid; i < 1156; i += 256) sts128(XHu + i * 16, make_uint4(0, 0, 0, 0));
    if (tid < 32) {
        sS1[tid] = g_gs1[e * 32 + tid];
        sQ1[tid] = g_gb1[e * 32 + tid];
    }
    if (tid < 64) {
        sS2[tid] = g_gs2[e * 64 + tid];
        sQ2[tid] = g_gb2[e * 64 + tid];
    }
    __syncthreads();

    // ---- phase 1: stage XH interior (x->fp16), W1H, and all 9 B2 tap tiles ----
    {
        const float* xb = x + (size_t)b * 3072;
#pragma unroll
        for (int it = 0; it < 4; it++) {
            int pp = tid + it * 256;              // position 0..1023
            float v0 = xb[pp];
            float v1 = xb[1024 + pp];
            float v2 = xb[2048 + pp];
            uint4 u;
            u.x = h2pack(v0, v1);
            u.y = (uint32_t)__half_as_ushort(__float2half_rn(v2));
            u.z = 0; u.w = 0;
            int y = pp >> 5, xx = pp & 31;
            sts128(XHu + (uint32_t)(((y + 1) * 34 + xx + 1) * 16), u);
        }
        const uint4* w1src = (const uint4*)(g_w1h) + (size_t)e * 9 * 32;   // 288 uint4
        for (int i = tid; i < 288; i += 256)
            sts128(W1Hu + (uint32_t)(i * 16), w1src[i]);
        const uint4* w2src = (const uint4*)(g_w2h) + (size_t)e * 9 * 256;  // 2304 uint4
#pragma unroll
        for (int j = 0; j < 9; j++) {
            int i = tid + j * 256;
            sts128(B2u + (uint32_t)((i >> 2) * A_STRIDE + (i & 3) * 16), w2src[i]);
        }
    }
    __syncthreads();

    // ---- phase 2: conv1 via fp16 mma (9 taps, m16n8k8), BN+ReLU+pool -> A rows ----
    {
        float s1v[4][2], q1v[4][2];
#pragma unroll
        for (int nt = 0; nt < 4; nt++) {
            int oc0 = nt * 8 + 2 * (lane & 3);
            s1v[nt][0] = sS1[oc0];     s1v[nt][1] = sS1[oc0 + 1];
            q1v[nt][0] = sQ1[oc0];     q1v[nt][1] = sQ1[oc0 + 1];
        }
        int rr  = (lane & 7) + ((lane >> 3) & 1) * 8;   // ldmatrix row within tile
        int cxA = lane >> 2;                            // c-frag row
        uint32_t baseB = W1Hu + (uint32_t)((((lane >> 3) & 3) * 8 + (lane & 7)) * 16);

#pragma unroll
        for (int grp = 0; grp < 2; grp++) {
            int cy = 2 * w + grp;                       // pooled row
            float ac[4][4][4];
#pragma unroll
            for (int d = 0; d < 4; d++)
#pragma unroll
                for (int nt = 0; nt < 4; nt++)
#pragma unroll
                    for (int j = 0; j < 4; j++) ac[d][nt][j] = 0.f;

            uint32_t baseA[2];
#pragma unroll
            for (int pp = 0; pp < 2; pp++) {
                int d = 2 * pp + (lane >> 4);
                baseA[pp] = XHu + (uint32_t)((((2 * cy + (d >> 1)) * 34) + 2 * rr + (d & 1)) * 16);
            }

#pragma unroll
            for (int tap = 0; tap < 9; tap++) {
                uint32_t off = (uint32_t)((((tap / 3) * 34) + (tap % 3)) * 16);
                uint32_t a0[4], a1[4], bf[4];
                ldm4(a0, baseA[0] + off);               // d-tiles 0,1
                ldm4(a1, baseA[1] + off);               // d-tiles 2,3
                ldm4(bf, baseB + (uint32_t)(tap * 512));
#pragma unroll
                for (int nt = 0; nt < 4; nt++) {
                    mma1688(ac[0][nt], a0[0], a0[1], bf[nt]);
                    mma1688(ac[1][nt], a0[2], a0[3], bf[nt]);
                    mma1688(ac[2][nt], a1[0], a1[1], bf[nt]);
                    mma1688(ac[3][nt], a1[2], a1[3], bf[nt]);
                }
            }

            // epilogue: pool over d in-register, BN+ReLU, store fp16 A rows
            int s0 = (cy + 1) * 18 + (cxA + 1);
            int s1 = s0 + 8;
#pragma unroll
            for (int nt = 0; nt < 4; nt++) {
                float m00 = 0.f, m01 = 0.f, m10 = 0.f, m11 = 0.f;
#pragma unroll
                for (int d = 0; d < 4; d++) {
                    m00 = fmaxf(m00, fmaxf(0.f, ac[d][nt][0] * s1v[nt][0] + q1v[nt][0]));
                    m01 = fmaxf(m01, fmaxf(0.f, ac[d][nt][1] * s1v[nt][1] + q1v[nt][1]));
                    m10 = fmaxf(m10, fmaxf(0.f, ac[d][nt][2] * s1v[nt][0] + q1v[nt][0]));
                    m11 = fmaxf(m11, fmaxf(0.f, ac[d][nt][3] * s1v[nt][1] + q1v[nt][1]));
                }
                int oc0 = nt * 8 + 2 * (lane & 3);
                sts32(Au + (uint32_t)(s0 * A_STRIDE + 2 * oc0), h2pack(m00, m01));
                sts32(Au + (uint32_t)(s1 * A_STRIDE + 2 * oc0), h2pack(m10, m11));
            }
        }
    }
    __syncthreads();

    // ---- phase 3: conv2 via fp16 mma (9 taps, m16n8k16), unroll for ILP ----
    int xl   = lane & 15;
    int colh = lane >> 4;
    uint32_t b_lane = (uint32_t)((((lane >> 4) * 8 + (lane & 7)) * A_STRIDE) + ((lane >> 3) & 1) * 16);

    float acc[2][8][4];
#pragma unroll
    for (int mt = 0; mt < 2; mt++)
#pragma unroll
        for (int nt = 0; nt < 8; nt++)
#pragma unroll
            for (int j = 0; j < 4; j++) acc[mt][nt][j] = 0.f;

#pragma unroll 3
    for (int tap = 0; tap < 9; tap++) {
        uint32_t Bc = B2u + (uint32_t)(tap * 5120);
        int ky = tap / 3, kx = tap % 3;
        uint32_t arow0 = Au + (uint32_t)((((2 * w + ky) * 18) + xl + kx) * A_STRIDE + colh * 16);
        uint32_t arow1 = arow0 + 18 * A_STRIDE;

#pragma unroll
        for (int kc = 0; kc < 2; kc++) {
            uint32_t ko = kc * 32;
            uint32_t a0[4], a1[4];
            ldm4(a0, arow0 + ko);
            ldm4(a1, arow1 + ko);

            uint32_t bf[8][2];
#pragma unroll
            for (int g = 0; g < 4; g++) {
                uint32_t r[4];
                ldm4(r, Bc + b_lane + (uint32_t)(g * 16 * A_STRIDE) + ko);
                bf[g * 2][0] = r[0]; bf[g * 2][1] = r[1];
                bf[g * 2 + 1][0] = r[2]; bf[g * 2 + 1][1] = r[3];
            }
#pragma unroll
            for (int nt = 0; nt < 8; nt++) {
                mma16816(acc[0][nt], a0, bf[nt]);
                mma16816(acc[1][nt], a1, bf[nt]);
            }
        }
    }
    __syncthreads();

    // ---- phase 4: BN + ReLU + 2x2 pool (warp-local) -> h2s smem ----
    {
        int c0b  = 2 * (lane & 3);
        bool act = ((lane >> 2) & 1) == 0;
        int pos0 = w * 8 + (lane >> 3);       // pooled flat pos (py=w, px=lane>>3)
        int pos1 = pos0 + 4;
#pragma unroll
        for (int nt = 0; nt < 8; nt++) {
            int c0 = nt * 8 + c0b, c1 = c0 + 1;
            float s0 = sS2[c0], s1 = sS2[c1], q0 = sQ2[c0], q1 = sQ2[c1];
            float v0 = fmaxf(fmaxf(0.f, acc[0][nt][0] * s0 + q0), fmaxf(0.f, acc[1][nt][0] * s0 + q0));
            float v1 = fmaxf(fmaxf(0.f, acc[0][nt][1] * s1 + q1), fmaxf(0.f, acc[1][nt][1] * s1 + q1));
            float v2 = fmaxf(fmaxf(0.f, acc[0][nt][2] * s0 + q0), fmaxf(0.f, acc[1][nt][2] * s0 + q0));
            float v3 = fmaxf(fmaxf(0.f, acc[0][nt][3] * s1 + q1), fmaxf(0.f, acc[1][nt][3] * s1 + q1));
            v0 = fmaxf(v0, __shfl_xor_sync(0xffffffffu, v0, 4));
            v1 = fmaxf(v1, __shfl_xor_sync(0xffffffffu, v1, 4));
            v2 = fmaxf(v2, __shfl_xor_sync(0xffffffffu, v2, 4));
            v3 = fmaxf(v3, __shfl_xor_sync(0xffffffffu, v3, 4));
            if (act) {
                h2s[c0 * 64 + pos0] = v0;
                h2s[c1 * 64 + pos0] = v1;
                h2s[c0 * 64 + pos1] = v2;
                h2s[c1 * 64 + pos1] = v3;
            }
        }
    }
    __syncthreads();

    // ---- phase 5: coalesced fc GEMV with fp16 weights ----
    const uint4* feh = (const uint4*)(g_fcwh) + (size_t)e * 5120;   // 10 x 512 uint4
    const float4* h2s4 = (const float4*)h2s;
    float fca[10];
#pragma unroll
    for (int o = 0; o < 10; o++) fca[o] = 0.f;
#pragma unroll
    for (int it = 0; it < 2; it++) {
        int j8 = it * 256 + tid;                  // 8-float stripe index 0..511
        float4 ha = h2s4[2 * j8];
        float4 hb = h2s4[2 * j8 + 1];
#pragma unroll
        for (int o = 0; o < 10; o++) {
            uint4 wv = feh[o * 512 + j8];
            float2 w0 = __half22float2(*(const __half2*)&wv.x);
            float2 w1 = __half22float2(*(const __half2*)&wv.y);
            float2 w2v = __half22float2(*(const __half2*)&wv.z);
            float2 w3 = __half22float2(*(const __half2*)&wv.w);
            fca[o] += ha.x * w0.x + ha.y * w0.y + ha.z * w1.x + ha.w * w1.y
                    + hb.x * w2v.x + hb.y * w2v.y + hb.z * w3.x + hb.w * w3.y;
        }
    }

    // ---- phase 6: reduce fc partials, write pair output ----
#pragma unroll
    for (int o = 0; o < 10; o++)
#pragma unroll
        for (int off = 16; off; off >>= 1)
            fca[o] += __shfl_xor_sync(0xffffffffu, fca[o], off);

    if (lane == 0)
#pragma unroll
        for (int o = 0; o < 10; o++) redm[w * 10 + o] = fca[o];
    __syncthreads();
    if (tid < 10) {
        float s = 0.f;
#pragma unroll
        for (int ww = 0; ww < 8; ww++) s += redm[ww * 10 + tid];
        g_pout[p * 10 + tid] = s + fcb[e * 10 + tid];
    }
}

// ---------------- combine: y = log(g0*exp(o0) + g1*exp(o1)) ----------------
__global__ void combine_kernel(float* __restrict__ out) {
    int idx = blockIdx.x * blockDim.x + threadIdx.x;
    if (idx >= BATCH * 10) return;
    int b = idx / 10, o = idx - b * 10;
    float g0 = g_gatev[2 * b], g1 = g_gatev[2 * b + 1];
    float c = g0 * expf(g_pout[(2 * b) * 10 + o]) + g1 * expf(g_pout[(2 * b + 1) * 10 + o]);
    if (c == 0.f) c = 2.2204460492503131e-16f;   // np.finfo(float).eps
    out[idx] = logf(c);
}

// ---------------- loss: CV^2(importance) + CV^2(load), deterministic ----------------
__global__ void loss_kernel(float* __restrict__ out, int out_size) {
    __shared__ float rimp[8 * 8];
    __shared__ float rcnt[8 * 8];
    int t = threadIdx.x;   // 256
    float imp[8], cnt[8];
#pragma unroll
    for (int i = 0; i < 8; i++) { imp[i] = 0.f; cnt[i] = 0.f; }
    for (int p = t; p < 2 * BATCH; p += 256) {
        int e = g_expid[p];
        imp[e] += g_gatev[p];
        cnt[e] += 1.f;
    }
#pragma unroll
    for (int off = 16; off; off >>= 1)
#pragma unroll
        for (int i = 0; i < 8; i++) {
            imp[i] += __shfl_xor_sync(0xffffffffu, imp[i], off);
            cnt[i] += __shfl_xor_sync(0xffffffffu, cnt[i], off);
        }
    if ((t & 31) == 0)
#pragma unroll
        for (int i = 0; i < 8; i++) {
            rimp[(t >> 5) * 8 + i] = imp[i];
            rcnt[(t >> 5) * 8 + i] = cnt[i];
        }
    __syncthreads();
    if (t == 0) {
        double si = 0, sl = 0, si2 = 0, sl2 = 0;
        for (int e = 0; e < 8; e++) {
            double vi = 0, vl = 0;
            for (int w = 0; w < 8; w++) { vi += rimp[w * 8 + e]; vl += rcnt[w * 8 + e]; }
            si += vi; sl += vl; si2 += vi * vi; sl2 += vl * vl;
        }
        double mi = si / 8.0, ml = sl / 8.0;
        double vari = (si2 - 8.0 * mi * mi) / 7.0;   // ddof=1
        double varl = (sl2 - 8.0 * ml * ml) / 7.0;
        double loss = (vari / (mi * mi + 1e-10) + varl / (ml * ml + 1e-10)) * 0.01;
        out[out_size - 1] = (float)loss;
    }
}

// ---------------- launch ----------------
extern "C" void kernel_launch(void* const* d_in, const int* in_sizes, int n_in,
                              void* d_out, int out_size) {
    const float* x   = (const float*)d_in[0];
    // d_in[1] = index (unused by reference math)
    const float* wg  = (const float*)d_in[2];
    const float* w1  = (const float*)d_in[3];
    const float* b1  = (const float*)d_in[4];
    const float* g1  = (const float*)d_in[5];
    const float* be1 = (const float*)d_in[6];
    const float* rm1 = (const float*)d_in[7];
    const float* rv1 = (const float*)d_in[8];
    const float* w2  = (const float*)d_in[9];
    const float* b2  = (const float*)d_in[10];
    const float* g2  = (const float*)d_in[11];
    const float* be2 = (const float*)d_in[12];
    const float* rm2 = (const float*)d_in[13];
    const float* rv2 = (const float*)d_in[14];
    const float* fcw = (const float*)d_in[15];
    const float* fcb = (const float*)d_in[16];
    float* out = (float*)d_out;

    cudaFuncSetAttribute(pair_kernel, cudaFuncAttributeMaxDynamicSharedMemorySize, SMEM_BYTES);

    eff_kernel<<<1, 512>>>(b1, g1, be1, rm1, rv1, b2, g2, be2, rm2, rv2);
    w2h_kernel<<<576, 256>>>(w2);
    w1h_kernel<<<27, 256>>>(w1);
    fcwh_kernel<<<1280, 256>>>(fcw);
    gate_kernel<<<BATCH / GS, 256>>>(x, wg);
    pair_kernel<<<2 * BATCH, 256, SMEM_BYTES>>>(x, fcb);
    combine_kernel<<<(BATCH * 10 + 255) / 256, 256>>>(out);
    loss_kernel<<<1, 256>>>(out, out_size);
}